// round 2
// baseline (speedup 1.0000x reference)
#include <cuda_runtime.h>
#include <cstdint>

#define BB   4
#define TT   2048
#define EMB  1024
#define NH   16
#define HD   64
#define DFF  4096
#define MR   (BB*TT)   // 8192 rows

#define NEG_INF (__int_as_float(0xff800000))

// ---------------- scratch (static device globals; no allocation) ----------------
__device__ float g_qkv [(size_t)MR * 3 * EMB];  // 96 MB
__device__ float g_att [(size_t)MR * EMB];      // 32 MB
__device__ float g_res1[(size_t)MR * EMB];
__device__ float g_x1  [(size_t)MR * EMB];
__device__ float g_ff  [(size_t)MR * DFF];      // 128 MB
__device__ float g_res2[(size_t)MR * EMB];

// ---------------- GEMM: C[M,N] = A[M,K]@B[K,N] + bias (+resid) (+relu) -----------
// 128x128 tile, BK=16, 256 threads, 8x8 microtile per thread.
template<int KD, bool RELU, bool RESID>
__global__ __launch_bounds__(256)
void gemm_kernel(const float* __restrict__ A, const float* __restrict__ Bm,
                 const float* __restrict__ bias, const float* __restrict__ Rm,
                 float* __restrict__ C, int N)
{
    __shared__ float As[16][128];
    __shared__ float Bs[16][128];

    const int tid = threadIdx.x;
    const int tx = tid & 15, ty = tid >> 4;
    const int mBase = blockIdx.y * 128, nBase = blockIdx.x * 128;
    const int arow = tid >> 2, acol = (tid & 3) << 2;   // A: 128 rows x 16 k
    const int brow = tid >> 5, bcol = (tid & 31) << 2;  // B: 16 k x 128 cols

    float acc[8][8];
    #pragma unroll
    for (int i = 0; i < 8; i++)
        #pragma unroll
        for (int j = 0; j < 8; j++) acc[i][j] = 0.f;

    for (int k0 = 0; k0 < KD; k0 += 16) {
        #pragma unroll
        for (int h = 0; h < 2; h++) {
            float4 v = *(const float4*)(A + (size_t)(mBase + arow + h*64)*KD + k0 + acol);
            As[acol+0][arow + h*64] = v.x;
            As[acol+1][arow + h*64] = v.y;
            As[acol+2][arow + h*64] = v.z;
            As[acol+3][arow + h*64] = v.w;
        }
        #pragma unroll
        for (int h = 0; h < 2; h++) {
            float4 v = *(const float4*)(Bm + (size_t)(k0 + brow + h*8)*N + nBase + bcol);
            *(float4*)&Bs[brow + h*8][bcol] = v;
        }
        __syncthreads();

        #pragma unroll
        for (int k = 0; k < 16; k++) {
            float af[8], bf[8];
            *(float4*)(af)     = *(const float4*)&As[k][ty*4];
            *(float4*)(af + 4) = *(const float4*)&As[k][ty*4 + 64];
            *(float4*)(bf)     = *(const float4*)&Bs[k][tx*4];
            *(float4*)(bf + 4) = *(const float4*)&Bs[k][tx*4 + 64];
            #pragma unroll
            for (int i = 0; i < 8; i++)
                #pragma unroll
                for (int j = 0; j < 8; j++)
                    acc[i][j] = fmaf(af[i], bf[j], acc[i][j]);
        }
        __syncthreads();
    }

    #pragma unroll
    for (int hi = 0; hi < 2; hi++)
    #pragma unroll
    for (int i2 = 0; i2 < 4; i2++) {
        const int row = mBase + hi*64 + ty*4 + i2;
        const int ii = hi*4 + i2;
        #pragma unroll
        for (int hj = 0; hj < 2; hj++) {
            const int col = nBase + hj*64 + tx*4;
            const int jj0 = hj*4;
            float4 bv = *(const float4*)(bias + col);
            float4 o;
            o.x = acc[ii][jj0+0] + bv.x;
            o.y = acc[ii][jj0+1] + bv.y;
            o.z = acc[ii][jj0+2] + bv.z;
            o.w = acc[ii][jj0+3] + bv.w;
            if (RESID) {
                float4 rv = *(const float4*)(Rm + (size_t)row*N + col);
                o.x += rv.x; o.y += rv.y; o.z += rv.z; o.w += rv.w;
            }
            if (RELU) {
                o.x = fmaxf(o.x, 0.f); o.y = fmaxf(o.y, 0.f);
                o.z = fmaxf(o.z, 0.f); o.w = fmaxf(o.w, 0.f);
            }
            *(float4*)(C + (size_t)row*N + col) = o;
        }
    }
}

// ---------------- Flash attention (fp32, causal, 64q x 64k tiles) ----------------
// qkv layout: row (b*T+t), cols [q:0..1024 | k:1024..2048 | v:2048..3072], head h at h*64.
// out written directly in [b,t,e] layout.
#define ATT_SMEM ((4*64*65 + 3*64) * 4)

__global__ __launch_bounds__(256)
void attn_kernel(const float* __restrict__ qkv, float* __restrict__ out)
{
    extern __shared__ float sm[];
    float* Qs = sm;                 // [64][65]
    float* Ks = Qs + 64*65;         // [64][65]
    float* Vs = Ks + 64*65;         // [64][65]
    float* Ps = Vs + 64*65;         // [64][65]
    float* mS = Ps + 64*65;         // [64]
    float* lS = mS + 64;            // [64]
    float* aS = lS + 64;            // [64]

    const int tid = threadIdx.x;
    const int tx = tid & 15, ty = tid >> 4;
    const int qi = blockIdx.x, h = blockIdx.y, b = blockIdx.z;
    const size_t rowBaseQ = (size_t)(b*TT + qi*64);

    // load Q tile
    const float* qb = qkv + rowBaseQ * 3072 + h*64;
    #pragma unroll
    for (int it = 0; it < 4; it++) {
        int f = tid + it*256;
        int r = f >> 4, c = (f & 15) << 2;
        float4 v = *(const float4*)(qb + (size_t)r*3072 + c);
        Qs[r*65 + c + 0] = v.x; Qs[r*65 + c + 1] = v.y;
        Qs[r*65 + c + 2] = v.z; Qs[r*65 + c + 3] = v.w;
    }
    if (tid < 64) { mS[tid] = NEG_INF; lS[tid] = 0.f; }

    float accO[4][4];
    #pragma unroll
    for (int i = 0; i < 4; i++)
        #pragma unroll
        for (int j = 0; j < 4; j++) accO[i][j] = 0.f;
    __syncthreads();

    for (int j = 0; j <= qi; j++) {
        const float* kb = qkv + (size_t)(b*TT + j*64)*3072 + EMB + h*64;
        const float* vb = kb + EMB;
        #pragma unroll
        for (int it = 0; it < 4; it++) {
            int f = tid + it*256;
            int r = f >> 4, c = (f & 15) << 2;
            float4 kv = *(const float4*)(kb + (size_t)r*3072 + c);
            float4 vv = *(const float4*)(vb + (size_t)r*3072 + c);
            Ks[r*65+c+0]=kv.x; Ks[r*65+c+1]=kv.y; Ks[r*65+c+2]=kv.z; Ks[r*65+c+3]=kv.w;
            Vs[r*65+c+0]=vv.x; Vs[r*65+c+1]=vv.y; Vs[r*65+c+2]=vv.z; Vs[r*65+c+3]=vv.w;
        }
        __syncthreads();

        // S = Q @ K^T (4x4 microtile: rows ty+16i, cols tx+16j)
        float sacc[4][4];
        #pragma unroll
        for (int i = 0; i < 4; i++)
            #pragma unroll
            for (int jj = 0; jj < 4; jj++) sacc[i][jj] = 0.f;
        #pragma unroll 8
        for (int k = 0; k < 64; k++) {
            float qf[4], kf[4];
            #pragma unroll
            for (int i = 0; i < 4; i++)  qf[i]  = Qs[(ty + 16*i)*65 + k];
            #pragma unroll
            for (int jj = 0; jj < 4; jj++) kf[jj] = Ks[(tx + 16*jj)*65 + k];
            #pragma unroll
            for (int i = 0; i < 4; i++)
                #pragma unroll
                for (int jj = 0; jj < 4; jj++)
                    sacc[i][jj] = fmaf(qf[i], kf[jj], sacc[i][jj]);
        }
        const bool diag = (j == qi);
        #pragma unroll
        for (int i = 0; i < 4; i++)
            #pragma unroll
            for (int jj = 0; jj < 4; jj++) {
                int r = ty + 16*i, c = tx + 16*jj;
                float v = sacc[i][jj] * 0.125f;
                if (diag && c > r) v = NEG_INF;
                Ps[r*65 + c] = v;
            }
        __syncthreads();

        // online softmax: 4 threads per row
        {
            int r = tid >> 2, q = tid & 3;
            float mloc = NEG_INF;
            #pragma unroll
            for (int c = 0; c < 16; c++) mloc = fmaxf(mloc, Ps[r*65 + q*16 + c]);
            mloc = fmaxf(mloc, __shfl_xor_sync(0xffffffffu, mloc, 1));
            mloc = fmaxf(mloc, __shfl_xor_sync(0xffffffffu, mloc, 2));
            float mold = mS[r];
            float mnew = fmaxf(mold, mloc);
            float sloc = 0.f;
            #pragma unroll
            for (int c = 0; c < 16; c++) {
                float e = __expf(Ps[r*65 + q*16 + c] - mnew);
                Ps[r*65 + q*16 + c] = e;
                sloc += e;
            }
            sloc += __shfl_xor_sync(0xffffffffu, sloc, 1);
            sloc += __shfl_xor_sync(0xffffffffu, sloc, 2);
            if (q == 0) {
                float alpha = __expf(mold - mnew);
                lS[r] = lS[r]*alpha + sloc;
                mS[r] = mnew;
                aS[r] = alpha;
            }
        }
        __syncthreads();

        // rescale + O += P @ V
        #pragma unroll
        for (int i = 0; i < 4; i++) {
            float al = aS[ty + 16*i];
            #pragma unroll
            for (int jj = 0; jj < 4; jj++) accO[i][jj] *= al;
        }
        #pragma unroll 8
        for (int k = 0; k < 64; k++) {
            float pf[4], vf[4];
            #pragma unroll
            for (int i = 0; i < 4; i++)  pf[i]  = Ps[(ty + 16*i)*65 + k];
            #pragma unroll
            for (int jj = 0; jj < 4; jj++) vf[jj] = Vs[k*65 + tx + 16*jj];
            #pragma unroll
            for (int i = 0; i < 4; i++)
                #pragma unroll
                for (int jj = 0; jj < 4; jj++)
                    accO[i][jj] = fmaf(pf[i], vf[jj], accO[i][jj]);
        }
        __syncthreads();
    }

    #pragma unroll
    for (int i = 0; i < 4; i++) {
        int r = ty + 16*i;
        float inv = 1.f / lS[r];
        size_t orow = (rowBaseQ + r) * EMB + h*64;
        #pragma unroll
        for (int jj = 0; jj < 4; jj++)
            out[orow + tx + 16*jj] = accO[i][jj] * inv;
    }
}

// ---------------- LayerNorm over last dim (1024), one block per row ----------------
__global__ __launch_bounds__(256)
void ln_kernel(const float* __restrict__ in, const float* __restrict__ g,
               const float* __restrict__ bb, float* __restrict__ out)
{
    const int row = blockIdx.x, tid = threadIdx.x;
    const float* rp = in + (size_t)row * EMB;
    float4 v = *(const float4*)(rp + tid*4);
    float s  = v.x + v.y + v.z + v.w;
    float sq = v.x*v.x + v.y*v.y + v.z*v.z + v.w*v.w;
    #pragma unroll
    for (int o = 16; o > 0; o >>= 1) {
        s  += __shfl_xor_sync(0xffffffffu, s,  o);
        sq += __shfl_xor_sync(0xffffffffu, sq, o);
    }
    __shared__ float ws[8], wq[8], stat[2];
    const int w = tid >> 5;
    if ((tid & 31) == 0) { ws[w] = s; wq[w] = sq; }
    __syncthreads();
    if (tid == 0) {
        float ts = 0.f, tq = 0.f;
        #pragma unroll
        for (int i = 0; i < 8; i++) { ts += ws[i]; tq += wq[i]; }
        float mean = ts * (1.f/EMB);
        float var  = tq * (1.f/EMB) - mean*mean;
        stat[0] = mean;
        stat[1] = rsqrtf(var + 1e-5f);
    }
    __syncthreads();
    const float mean = stat[0], rs = stat[1];
    float4 gv = *(const float4*)(g  + tid*4);
    float4 bv = *(const float4*)(bb + tid*4);
    float4 o;
    o.x = (v.x - mean)*rs*gv.x + bv.x;
    o.y = (v.y - mean)*rs*gv.y + bv.y;
    o.z = (v.z - mean)*rs*gv.z + bv.z;
    o.w = (v.w - mean)*rs*gv.w + bv.w;
    *(float4*)(out + (size_t)row*EMB + tid*4) = o;
}

// ---------------- launch ----------------
extern "C" void kernel_launch(void* const* d_in, const int* in_sizes, int n_in,
                              void* d_out, int out_size)
{
    const float* x   = (const float*)d_in[0];
    const float* wat = (const float*)d_in[1];
    const float* bat = (const float*)d_in[2];
    const float* wpr = (const float*)d_in[3];
    const float* bpr = (const float*)d_in[4];
    const float* l1g = (const float*)d_in[5];
    const float* l1b = (const float*)d_in[6];
    const float* wf1 = (const float*)d_in[7];
    const float* bf1 = (const float*)d_in[8];
    const float* wf2 = (const float*)d_in[9];
    const float* bf2 = (const float*)d_in[10];
    const float* l2g = (const float*)d_in[11];
    const float* l2b = (const float*)d_in[12];

    static float *qkv = nullptr, *att, *res1, *x1, *ff, *res2;
    if (!qkv) {
        cudaGetSymbolAddress((void**)&qkv,  g_qkv);
        cudaGetSymbolAddress((void**)&att,  g_att);
        cudaGetSymbolAddress((void**)&res1, g_res1);
        cudaGetSymbolAddress((void**)&x1,   g_x1);
        cudaGetSymbolAddress((void**)&ff,   g_ff);
        cudaGetSymbolAddress((void**)&res2, g_res2);
        cudaFuncSetAttribute(attn_kernel, cudaFuncAttributeMaxDynamicSharedMemorySize, ATT_SMEM);
    }

    // 1. QKV projection: [8192,1024]@[1024,3072]
    gemm_kernel<EMB, false, false><<<dim3(3*EMB/128, MR/128), 256>>>(x, wat, bat, nullptr, qkv, 3*EMB);
    // 2. causal flash attention -> [b,t,e]
    attn_kernel<<<dim3(TT/64, NH, BB), 256, ATT_SMEM>>>(qkv, att);
    // 3. output proj + residual(x)
    gemm_kernel<EMB, false, true><<<dim3(EMB/128, MR/128), 256>>>(att, wpr, bpr, x, res1, EMB);
    // 4. LN1
    ln_kernel<<<MR, 256>>>(res1, l1g, l1b, x1);
    // 5. FF1 + ReLU: [8192,1024]@[1024,4096]
    gemm_kernel<EMB, true, false><<<dim3(DFF/128, MR/128), 256>>>(x1, wf1, bf1, nullptr, ff, DFF);
    // 6. FF2 + residual(x1): [8192,4096]@[4096,1024]
    gemm_kernel<DFF, false, true><<<dim3(EMB/128, MR/128), 256>>>(ff, wf2, bf2, x1, res2, EMB);
    // 7. LN2 -> out
    ln_kernel<<<MR, 256>>>(res2, l2g, l2b, (float*)d_out);
}

// round 6
// speedup vs baseline: 2.8594x; 2.8594x over previous
#include <cuda_runtime.h>
#include <cstdint>

#define BB   4
#define TT   2048
#define EMB  1024
#define NH   16
#define DFF  4096
#define MR   (BB*TT)   // 8192 rows

#define NEG_INF (__int_as_float(0xff800000))

// ---------------- scratch (static device globals; no allocation) ----------------
__device__ float g_qkv [(size_t)MR * 3 * EMB];
__device__ float g_att [(size_t)MR * EMB];
__device__ float g_res1[(size_t)MR * EMB];
__device__ float g_x1  [(size_t)MR * EMB];
__device__ float g_ff  [(size_t)MR * DFF];
__device__ float g_res2[(size_t)MR * EMB];
// transposed (tf32-rounded) weights: [N, K] row-major (K-major operand)
__device__ float g_watT[(size_t)3*EMB * EMB];
__device__ float g_wprT[(size_t)EMB * EMB];
__device__ float g_wf1T[(size_t)DFF * EMB];
__device__ float g_wf2T[(size_t)EMB * DFF];

// ================= helpers =================
static __device__ __forceinline__ uint32_t cvt_rna(float f) {
    uint32_t o;
    asm("cvt.rna.tf32.f32 %0, %1;" : "=r"(o) : "f"(f));
    return o;
}
static __device__ __forceinline__ float tf32r(float f) {
    return __uint_as_float(cvt_rna(f));
}
// D += A@B  (m16n8k8, tf32 inputs as b32, fp32 accum)
static __device__ __forceinline__ void mma16n8k8(float* d, const uint32_t* a, const uint32_t* b) {
    asm volatile(
        "mma.sync.aligned.m16n8k8.row.col.f32.tf32.tf32.f32 "
        "{%0,%1,%2,%3}, {%4,%5,%6,%7}, {%8,%9}, {%0,%1,%2,%3};"
        : "+f"(d[0]), "+f"(d[1]), "+f"(d[2]), "+f"(d[3])
        : "r"(a[0]), "r"(a[1]), "r"(a[2]), "r"(a[3]), "r"(b[0]), "r"(b[1]));
}

// ================= weight transpose + tf32 round =================
// in: [K, N] row-major -> out: [N, K] row-major, RNA-rounded
__global__ __launch_bounds__(256)
void transpose_cvt(const float* __restrict__ in, float* __restrict__ out, int K, int N)
{
    __shared__ float t[32][33];
    const int n0 = blockIdx.x * 32, k0 = blockIdx.y * 32;
    const int tx = threadIdx.x, ty = threadIdx.y;
    #pragma unroll
    for (int i = 0; i < 32; i += 8)
        t[ty + i][tx] = in[(size_t)(k0 + ty + i) * N + n0 + tx];
    __syncthreads();
    #pragma unroll
    for (int i = 0; i < 32; i += 8)
        out[(size_t)(n0 + ty + i) * K + k0 + tx] = tf32r(t[tx][ty + i]);
}

// ================= tf32 mma GEMM =================
// C[M,N] = A[M,K] @ Bt[N,K]^T + bias (+resid)(+relu)
// block 128x128, BK=32, 256 thr, warp grid 2(m) x 4(n), warp tile 64x32.
template<bool RELU, bool RESID>
__global__ __launch_bounds__(256, 2)
void gemm_mma(const float* __restrict__ A, const float* __restrict__ Bt,
              const float* __restrict__ bias, const float* __restrict__ Rm,
              float* __restrict__ C, int N, int K)
{
    __shared__ float As[128][36];   // [row][k], pad 36 -> conflict-free frags
    __shared__ float Bs[128][36];   // [col][k]

    const int tid = threadIdx.x;
    const int wid = tid >> 5, lane = tid & 31;
    const int wm = wid >> 2, wn = wid & 3;
    const int g = lane >> 2, q = lane & 3;
    const int mBase = blockIdx.y << 7, nBase = blockIdx.x << 7;
    const int r0 = tid >> 3, c4 = (tid & 7) << 2;

    const float* ap = A  + (size_t)(mBase + r0) * K + c4;
    const float* bp = Bt + (size_t)(nBase + r0) * K + c4;

    float acc[16][4];
    #pragma unroll
    for (int i = 0; i < 16; i++)
        #pragma unroll
        for (int j = 0; j < 4; j++) acc[i][j] = 0.f;

    for (int k0 = 0; k0 < K; k0 += 32) {
        #pragma unroll
        for (int i = 0; i < 4; i++) {
            float4 va = *(const float4*)(ap + (size_t)(32*i)*K + k0);
            float4 vb = *(const float4*)(bp + (size_t)(32*i)*K + k0);
            *(float4*)&As[r0 + 32*i][c4] =
                make_float4(tf32r(va.x), tf32r(va.y), tf32r(va.z), tf32r(va.w));
            *(float4*)&Bs[r0 + 32*i][c4] =
                make_float4(tf32r(vb.x), tf32r(vb.y), tf32r(vb.z), tf32r(vb.w));
        }
        __syncthreads();

        #pragma unroll
        for (int ks = 0; ks < 4; ks++) {
            const int kk = ks * 8;
            uint32_t af[4][4], bf[4][2];
            #pragma unroll
            for (int mt = 0; mt < 4; mt++) {
                const int rb = wm*64 + mt*16;
                af[mt][0] = __float_as_uint(As[rb + g    ][kk + q    ]);
                af[mt][1] = __float_as_uint(As[rb + g + 8][kk + q    ]);
                af[mt][2] = __float_as_uint(As[rb + g    ][kk + q + 4]);
                af[mt][3] = __float_as_uint(As[rb + g + 8][kk + q + 4]);
            }
            #pragma unroll
            for (int nt = 0; nt < 4; nt++) {
                const int cb = wn*32 + nt*8;
                bf[nt][0] = __float_as_uint(Bs[cb + g][kk + q    ]);
                bf[nt][1] = __float_as_uint(Bs[cb + g][kk + q + 4]);
            }
            #pragma unroll
            for (int mt = 0; mt < 4; mt++)
                #pragma unroll
                for (int nt = 0; nt < 4; nt++)
                    mma16n8k8(acc[mt*4 + nt], af[mt], bf[nt]);
        }
        __syncthreads();
    }

    // epilogue
    #pragma unroll
    for (int mt = 0; mt < 4; mt++) {
        const int row0 = mBase + wm*64 + mt*16 + g;
        #pragma unroll
        for (int nt = 0; nt < 4; nt++) {
            const int col = nBase + wn*32 + nt*8 + 2*q;
            const float* a4 = acc[mt*4 + nt];
            float2 bv = *(const float2*)(bias + col);
            float o0 = a4[0] + bv.x, o1 = a4[1] + bv.y;
            float o2 = a4[2] + bv.x, o3 = a4[3] + bv.y;
            if (RESID) {
                float2 u = *(const float2*)(Rm + (size_t)row0*N + col);
                float2 v = *(const float2*)(Rm + (size_t)(row0+8)*N + col);
                o0 += u.x; o1 += u.y; o2 += v.x; o3 += v.y;
            }
            if (RELU) {
                o0 = fmaxf(o0, 0.f); o1 = fmaxf(o1, 0.f);
                o2 = fmaxf(o2, 0.f); o3 = fmaxf(o3, 0.f);
            }
            *(float2*)(C + (size_t)row0*N + col)     = make_float2(o0, o1);
            *(float2*)(C + (size_t)(row0+8)*N + col) = make_float2(o2, o3);
        }
    }
}

// ---------------- Flash attention (tf32 mma, causal, 64q x 64k tiles) ----------------
#define AP 68   // smem pitch (floats) for 64-wide tiles
#define ATT_SMEM ((4*64*AP + 3*64) * 4)

__global__ __launch_bounds__(256)
void attn_kernel(const float* __restrict__ qkv, float* __restrict__ out)
{
    extern __shared__ float sm[];
    float* Qs = sm;                 // [64][AP]
    float* Ks = Qs + 64*AP;
    float* Vs = Ks + 64*AP;
    float* Ps = Vs + 64*AP;
    float* mS = Ps + 64*AP;
    float* lS = mS + 64;
    float* aS = lS + 64;

    const int tid = threadIdx.x;
    const int wid = tid >> 5, lane = tid & 31;
    const int wm = wid >> 2, wn = wid & 3;      // warp tile 32(m) x 16(n)
    const int g = lane >> 2, q = lane & 3;
    const int qi = blockIdx.x, h = blockIdx.y, b = blockIdx.z;
    const size_t rowBaseQ = (size_t)(b*TT + qi*64);

    // load Q tile (tf32-rounded)
    const float* qb = qkv + rowBaseQ * 3072 + h*64;
    #pragma unroll
    for (int it = 0; it < 4; it++) {
        int f = tid + it*256;
        int r = f >> 4, c = (f & 15) << 2;
        float4 v = *(const float4*)(qb + (size_t)r*3072 + c);
        *(float4*)&Qs[r*AP + c] = make_float4(tf32r(v.x), tf32r(v.y), tf32r(v.z), tf32r(v.w));
    }
    if (tid < 64) { mS[tid] = NEG_INF; lS[tid] = 0.f; }

    float accO[4][4];       // [mt*2+nt][4]
    #pragma unroll
    for (int i = 0; i < 4; i++)
        #pragma unroll
        for (int j = 0; j < 4; j++) accO[i][j] = 0.f;
    __syncthreads();

    for (int j = 0; j <= qi; j++) {
        const float* kb = qkv + (size_t)(b*TT + j*64)*3072 + EMB + h*64;
        const float* vb = kb + EMB;
        #pragma unroll
        for (int it = 0; it < 4; it++) {
            int f = tid + it*256;
            int r = f >> 4, c = (f & 15) << 2;
            float4 kv = *(const float4*)(kb + (size_t)r*3072 + c);
            float4 vv = *(const float4*)(vb + (size_t)r*3072 + c);
            *(float4*)&Ks[r*AP + c] = make_float4(tf32r(kv.x), tf32r(kv.y), tf32r(kv.z), tf32r(kv.w));
            *(float4*)&Vs[r*AP + c] = make_float4(tf32r(vv.x), tf32r(vv.y), tf32r(vv.z), tf32r(vv.w));
        }
        __syncthreads();

        // ---- S = Q @ K^T via mma (warp tile 32x16 => 2x2 m16n8 tiles) ----
        float sacc[4][4];
        #pragma unroll
        for (int i = 0; i < 4; i++)
            #pragma unroll
            for (int jj = 0; jj < 4; jj++) sacc[i][jj] = 0.f;

        #pragma unroll
        for (int ks = 0; ks < 8; ks++) {
            const int kk = ks * 8;
            uint32_t af[2][4], bf[2][2];
            #pragma unroll
            for (int mt = 0; mt < 2; mt++) {
                const int rb = wm*32 + mt*16;
                af[mt][0] = __float_as_uint(Qs[(rb + g    )*AP + kk + q    ]);
                af[mt][1] = __float_as_uint(Qs[(rb + g + 8)*AP + kk + q    ]);
                af[mt][2] = __float_as_uint(Qs[(rb + g    )*AP + kk + q + 4]);
                af[mt][3] = __float_as_uint(Qs[(rb + g + 8)*AP + kk + q + 4]);
            }
            #pragma unroll
            for (int nt = 0; nt < 2; nt++) {
                const int cb = wn*16 + nt*8;
                bf[nt][0] = __float_as_uint(Ks[(cb + g)*AP + kk + q    ]);
                bf[nt][1] = __float_as_uint(Ks[(cb + g)*AP + kk + q + 4]);
            }
            #pragma unroll
            for (int mt = 0; mt < 2; mt++)
                #pragma unroll
                for (int nt = 0; nt < 2; nt++)
                    mma16n8k8(sacc[mt*2 + nt], af[mt], bf[nt]);
        }

        // scale + causal mask + store S to Ps
        const bool diag = (j == qi);
        #pragma unroll
        for (int mt = 0; mt < 2; mt++) {
            #pragma unroll
            for (int nt = 0; nt < 2; nt++) {
                const int r0 = wm*32 + mt*16 + g;
                const int c0 = wn*16 + nt*8 + 2*q;
                float v0 = sacc[mt*2+nt][0] * 0.125f;
                float v1 = sacc[mt*2+nt][1] * 0.125f;
                float v2 = sacc[mt*2+nt][2] * 0.125f;
                float v3 = sacc[mt*2+nt][3] * 0.125f;
                if (diag) {
                    if (c0     > r0    ) v0 = NEG_INF;
                    if (c0 + 1 > r0    ) v1 = NEG_INF;
                    if (c0     > r0 + 8) v2 = NEG_INF;
                    if (c0 + 1 > r0 + 8) v3 = NEG_INF;
                }
                *(float2*)&Ps[r0*AP + c0]       = make_float2(v0, v1);
                *(float2*)&Ps[(r0 + 8)*AP + c0] = make_float2(v2, v3);
            }
        }
        __syncthreads();

        // ---- online softmax: 4 threads per row ----
        {
            int r = tid >> 2, qq = tid & 3;
            float mloc = NEG_INF;
            #pragma unroll
            for (int c = 0; c < 16; c++) mloc = fmaxf(mloc, Ps[r*AP + qq*16 + c]);
            mloc = fmaxf(mloc, __shfl_xor_sync(0xffffffffu, mloc, 1));
            mloc = fmaxf(mloc, __shfl_xor_sync(0xffffffffu, mloc, 2));
            float mold = mS[r];
            float mnew = fmaxf(mold, mloc);
            float sloc = 0.f;
            #pragma unroll
            for (int c = 0; c < 16; c++) {
                float e = tf32r(__expf(Ps[r*AP + qq*16 + c] - mnew));
                Ps[r*AP + qq*16 + c] = e;
                sloc += e;
            }
            sloc += __shfl_xor_sync(0xffffffffu, sloc, 1);
            sloc += __shfl_xor_sync(0xffffffffu, sloc, 2);
            if (qq == 0) {
                float alpha = __expf(mold - mnew);
                lS[r] = lS[r]*alpha + sloc;
                mS[r] = mnew;
                aS[r] = alpha;
            }
        }
        __syncthreads();

        // ---- rescale O, then O += P @ V via mma ----
        #pragma unroll
        for (int mt = 0; mt < 2; mt++) {
            float a0 = aS[wm*32 + mt*16 + g];
            float a1 = aS[wm*32 + mt*16 + g + 8];
            #pragma unroll
            for (int nt = 0; nt < 2; nt++) {
                accO[mt*2+nt][0] *= a0; accO[mt*2+nt][1] *= a0;
                accO[mt*2+nt][2] *= a1; accO[mt*2+nt][3] *= a1;
            }
        }
        #pragma unroll
        for (int ks = 0; ks < 8; ks++) {
            const int kk = ks * 8;
            uint32_t af[2][4], bf[2][2];
            #pragma unroll
            for (int mt = 0; mt < 2; mt++) {
                const int rb = wm*32 + mt*16;
                af[mt][0] = __float_as_uint(Ps[(rb + g    )*AP + kk + q    ]);
                af[mt][1] = __float_as_uint(Ps[(rb + g + 8)*AP + kk + q    ]);
                af[mt][2] = __float_as_uint(Ps[(rb + g    )*AP + kk + q + 4]);
                af[mt][3] = __float_as_uint(Ps[(rb + g + 8)*AP + kk + q + 4]);
            }
            #pragma unroll
            for (int nt = 0; nt < 2; nt++) {
                const int cb = wn*16 + nt*8;
                bf[nt][0] = __float_as_uint(Vs[(kk + q    )*AP + cb + g]);
                bf[nt][1] = __float_as_uint(Vs[(kk + q + 4)*AP + cb + g]);
            }
            #pragma unroll
            for (int mt = 0; mt < 2; mt++)
                #pragma unroll
                for (int nt = 0; nt < 2; nt++)
                    mma16n8k8(accO[mt*2 + nt], af[mt], bf[nt]);
        }
        __syncthreads();
    }

    // final: divide by l, write out (out is [b,t,e])
    #pragma unroll
    for (int mt = 0; mt < 2; mt++) {
        const int r = wm*32 + mt*16 + g;
        const float inv0 = 1.f / lS[r];
        const float inv1 = 1.f / lS[r + 8];
        #pragma unroll
        for (int nt = 0; nt < 2; nt++) {
            const int c = wn*16 + nt*8 + 2*q;
            const float* a4 = accO[mt*2 + nt];
            *(float2*)(out + (rowBaseQ + r    )*EMB + h*64 + c) = make_float2(a4[0]*inv0, a4[1]*inv0);
            *(float2*)(out + (rowBaseQ + r + 8)*EMB + h*64 + c) = make_float2(a4[2]*inv1, a4[3]*inv1);
        }
    }
}

// ---------------- LayerNorm over last dim (1024) ----------------
__global__ __launch_bounds__(256)
void ln_kernel(const float* __restrict__ in, const float* __restrict__ g,
               const float* __restrict__ bb, float* __restrict__ out)
{
    const int row = blockIdx.x, tid = threadIdx.x;
    const float* rp = in + (size_t)row * EMB;
    float4 v = *(const float4*)(rp + tid*4);
    float s  = v.x + v.y + v.z + v.w;
    float sq = v.x*v.x + v.y*v.y + v.z*v.z + v.w*v.w;
    #pragma unroll
    for (int o = 16; o > 0; o >>= 1) {
        s  += __shfl_xor_sync(0xffffffffu, s,  o);
        sq += __shfl_xor_sync(0xffffffffu, sq, o);
    }
    __shared__ float ws[8], wq[8], stat[2];
    const int w = tid >> 5;
    if ((tid & 31) == 0) { ws[w] = s; wq[w] = sq; }
    __syncthreads();
    if (tid == 0) {
        float ts = 0.f, tq = 0.f;
        #pragma unroll
        for (int i = 0; i < 8; i++) { ts += ws[i]; tq += wq[i]; }
        float mean = ts * (1.f/EMB);
        float var  = tq * (1.f/EMB) - mean*mean;
        stat[0] = mean;
        stat[1] = rsqrtf(var + 1e-5f);
    }
    __syncthreads();
    const float mean = stat[0], rs = stat[1];
    float4 gv = *(const float4*)(g  + tid*4);
    float4 bv = *(const float4*)(bb + tid*4);
    float4 o;
    o.x = (v.x - mean)*rs*gv.x + bv.x;
    o.y = (v.y - mean)*rs*gv.y + bv.y;
    o.z = (v.z - mean)*rs*gv.z + bv.z;
    o.w = (v.w - mean)*rs*gv.w + bv.w;
    *(float4*)(out + (size_t)row*EMB + tid*4) = o;
}

// ---------------- launch ----------------
extern "C" void kernel_launch(void* const* d_in, const int* in_sizes, int n_in,
                              void* d_out, int out_size)
{
    const float* x   = (const float*)d_in[0];
    const float* wat = (const float*)d_in[1];
    const float* bat = (const float*)d_in[2];
    const float* wpr = (const float*)d_in[3];
    const float* bpr = (const float*)d_in[4];
    const float* l1g = (const float*)d_in[5];
    const float* l1b = (const float*)d_in[6];
    const float* wf1 = (const float*)d_in[7];
    const float* bf1 = (const float*)d_in[8];
    const float* wf2 = (const float*)d_in[9];
    const float* bf2 = (const float*)d_in[10];
    const float* l2g = (const float*)d_in[11];
    const float* l2b = (const float*)d_in[12];

    static float *qkv = nullptr, *att, *res1, *x1, *ff, *res2, *watT, *wprT, *wf1T, *wf2T;
    if (!qkv) {
        cudaGetSymbolAddress((void**)&qkv,  g_qkv);
        cudaGetSymbolAddress((void**)&att,  g_att);
        cudaGetSymbolAddress((void**)&res1, g_res1);
        cudaGetSymbolAddress((void**)&x1,   g_x1);
        cudaGetSymbolAddress((void**)&ff,   g_ff);
        cudaGetSymbolAddress((void**)&res2, g_res2);
        cudaGetSymbolAddress((void**)&watT, g_watT);
        cudaGetSymbolAddress((void**)&wprT, g_wprT);
        cudaGetSymbolAddress((void**)&wf1T, g_wf1T);
        cudaGetSymbolAddress((void**)&wf2T, g_wf2T);
        cudaFuncSetAttribute(attn_kernel, cudaFuncAttributeMaxDynamicSharedMemorySize, ATT_SMEM);
    }

    // weight transpose + tf32 rounding: [K,N] -> [N,K]
    transpose_cvt<<<dim3(3*EMB/32, EMB/32), dim3(32,8)>>>(wat, watT, EMB, 3*EMB);
    transpose_cvt<<<dim3(EMB/32,   EMB/32), dim3(32,8)>>>(wpr, wprT, EMB, EMB);
    transpose_cvt<<<dim3(DFF/32,   EMB/32), dim3(32,8)>>>(wf1, wf1T, EMB, DFF);
    transpose_cvt<<<dim3(EMB/32,   DFF/32), dim3(32,8)>>>(wf2, wf2T, DFF, EMB);

    // 1. QKV projection
    gemm_mma<false,false><<<dim3(3*EMB/128, MR/128), 256>>>(x, watT, bat, nullptr, qkv, 3*EMB, EMB);
    // 2. causal flash attention
    attn_kernel<<<dim3(TT/64, NH, BB), 256, ATT_SMEM>>>(qkv, att);
    // 3. output proj + residual(x)
    gemm_mma<false,true><<<dim3(EMB/128, MR/128), 256>>>(att, wprT, bpr, x, res1, EMB, EMB);
    // 4. LN1
    ln_kernel<<<MR, 256>>>(res1, l1g, l1b, x1);
    // 5. FF1 + ReLU
    gemm_mma<true,false><<<dim3(DFF/128, MR/128), 256>>>(x1, wf1T, bf1, nullptr, ff, DFF, EMB);
    // 6. FF2 + residual(x1)
    gemm_mma<false,true><<<dim3(EMB/128, MR/128), 256>>>(ff, wf2T, bf2, x1, res2, EMB, DFF);
    // 7. LN2 -> out
    ln_kernel<<<MR, 256>>>(res2, l2g, l2b, (float*)d_out);
}

// round 7
// speedup vs baseline: 3.3225x; 1.1620x over previous
#include <cuda_runtime.h>
#include <cstdint>

#define BB   4
#define TT   2048
#define EMB  1024
#define NH   16
#define DFF  4096
#define MR   (BB*TT)   // 8192 rows

#define NEG_INF (__int_as_float(0xff800000))

// ---------------- scratch (static device globals; no allocation) ----------------
__device__ float g_qkv [(size_t)MR * 3 * EMB];
__device__ float g_att [(size_t)MR * EMB];
__device__ float g_res1[(size_t)MR * EMB];
__device__ float g_x1  [(size_t)MR * EMB];
__device__ float g_ff  [(size_t)MR * DFF];
__device__ float g_res2[(size_t)MR * EMB];
// transposed (tf32-rounded) weights: [N, K] row-major (K-major operand)
__device__ float g_watT[(size_t)3*EMB * EMB];
__device__ float g_wprT[(size_t)EMB * EMB];
__device__ float g_wf1T[(size_t)DFF * EMB];
__device__ float g_wf2T[(size_t)EMB * DFF];

// ================= helpers =================
static __device__ __forceinline__ uint32_t cvt_rna(float f) {
    uint32_t o;
    asm("cvt.rna.tf32.f32 %0, %1;" : "=r"(o) : "f"(f));
    return o;
}
static __device__ __forceinline__ float tf32r(float f) {
    return __uint_as_float(cvt_rna(f));
}
static __device__ __forceinline__ uint32_t s2u(const void* p) {
    uint32_t a;
    asm("{ .reg .u64 t; cvta.to.shared.u64 t, %1; cvt.u32.u64 %0, t; }" : "=r"(a) : "l"(p));
    return a;
}
static __device__ __forceinline__ void cpa16(uint32_t s, const void* g) {
    asm volatile("cp.async.cg.shared.global [%0], [%1], 16;" :: "r"(s), "l"(g));
}
#define CP_COMMIT() asm volatile("cp.async.commit_group;" ::: "memory")
#define CP_WAIT(n)  asm volatile("cp.async.wait_group %0;" :: "n"(n) : "memory")

// D += A@B  (m16n8k8, tf32 inputs as b32, fp32 accum)
static __device__ __forceinline__ void mma16n8k8(float* d, const uint32_t* a, const uint32_t* b) {
    asm volatile(
        "mma.sync.aligned.m16n8k8.row.col.f32.tf32.tf32.f32 "
        "{%0,%1,%2,%3}, {%4,%5,%6,%7}, {%8,%9}, {%0,%1,%2,%3};"
        : "+f"(d[0]), "+f"(d[1]), "+f"(d[2]), "+f"(d[3])
        : "r"(a[0]), "r"(a[1]), "r"(a[2]), "r"(a[3]), "r"(b[0]), "r"(b[1]));
}

// ================= weight transpose + tf32 round =================
__global__ __launch_bounds__(256)
void transpose_cvt(const float* __restrict__ in, float* __restrict__ out, int K, int N)
{
    __shared__ float t[32][33];
    const int n0 = blockIdx.x * 32, k0 = blockIdx.y * 32;
    const int tx = threadIdx.x, ty = threadIdx.y;
    #pragma unroll
    for (int i = 0; i < 32; i += 8)
        t[ty + i][tx] = in[(size_t)(k0 + ty + i) * N + n0 + tx];
    __syncthreads();
    #pragma unroll
    for (int i = 0; i < 32; i += 8)
        out[(size_t)(n0 + ty + i) * K + k0 + tx] = tf32r(t[tx][ty + i]);
}

// ================= tf32 mma GEMM, cp.async 2-stage pipeline =================
// C[M,N] = A[M,K] @ Bt[N,K]^T + bias (+resid)(+relu)
// block 128x128, BK=32, 256 thr, warp grid 2(m) x 4(n), warp tile 64x32.
#define GP      36                 // smem pitch (floats)
#define GTILE   (128*GP)           // 4608 floats per tile-stage
#define GSMEM   (4*GTILE*4)        // bytes: A0,A1,B0,B1

template<bool RELU, bool RESID>
__global__ __launch_bounds__(256, 2)
void gemm_mma(const float* __restrict__ A, const float* __restrict__ Bt,
              const float* __restrict__ bias, const float* __restrict__ Rm,
              float* __restrict__ C, int N, int K)
{
    extern __shared__ float sg[];
    float* Asm = sg;                // [2][128][GP]
    float* Bsm = sg + 2*GTILE;

    const int tid = threadIdx.x;
    const int wid = tid >> 5, lane = tid & 31;
    const int wm = wid >> 2, wn = wid & 3;
    const int g = lane >> 2, q = lane & 3;
    const int mBase = blockIdx.y << 7, nBase = blockIdx.x << 7;
    const int lrow = tid >> 3, lc4 = (tid & 7) << 2;

    const float* ap = A  + (size_t)(mBase + lrow) * K + lc4;
    const float* bp = Bt + (size_t)(nBase + lrow) * K + lc4;
    const uint32_t sA0 = s2u(Asm) + (uint32_t)(lrow*GP + lc4) * 4;
    const uint32_t sB0 = s2u(Bsm) + (uint32_t)(lrow*GP + lc4) * 4;

    float acc[16][4];
    #pragma unroll
    for (int i = 0; i < 16; i++)
        #pragma unroll
        for (int j = 0; j < 4; j++) acc[i][j] = 0.f;

    const int nT = K >> 5;

    // prologue: stage 0
    #pragma unroll
    for (int i = 0; i < 4; i++) {
        cpa16(sA0 + (uint32_t)(32*i*GP)*4, ap + (size_t)(32*i)*K);
        cpa16(sB0 + (uint32_t)(32*i*GP)*4, bp + (size_t)(32*i)*K);
    }
    CP_COMMIT();

    #pragma unroll 1
    for (int t = 0; t < nT; ++t) {
        if (t + 1 < nT) {
            const int st = (t + 1) & 1;
            const size_t kof = (size_t)(t + 1) * 32;
            const uint32_t so = (uint32_t)(st * GTILE) * 4;
            #pragma unroll
            for (int i = 0; i < 4; i++) {
                cpa16(sA0 + so + (uint32_t)(32*i*GP)*4, ap + (size_t)(32*i)*K + kof);
                cpa16(sB0 + so + (uint32_t)(32*i*GP)*4, bp + (size_t)(32*i)*K + kof);
            }
            CP_COMMIT();
            CP_WAIT(1);
        } else {
            CP_WAIT(0);
        }
        __syncthreads();

        const float* As = Asm + (t & 1) * GTILE;
        const float* Bs = Bsm + (t & 1) * GTILE;

        #pragma unroll
        for (int ks = 0; ks < 4; ks++) {
            const int kk = ks * 8;
            uint32_t af[4][4], bf[4][2];
            #pragma unroll
            for (int mt = 0; mt < 4; mt++) {
                const int rb = wm*64 + mt*16;
                af[mt][0] = cvt_rna(As[(rb + g    )*GP + kk + q    ]);
                af[mt][1] = cvt_rna(As[(rb + g + 8)*GP + kk + q    ]);
                af[mt][2] = cvt_rna(As[(rb + g    )*GP + kk + q + 4]);
                af[mt][3] = cvt_rna(As[(rb + g + 8)*GP + kk + q + 4]);
            }
            #pragma unroll
            for (int nt = 0; nt < 4; nt++) {
                const int cb = wn*32 + nt*8;
                bf[nt][0] = __float_as_uint(Bs[(cb + g)*GP + kk + q    ]);
                bf[nt][1] = __float_as_uint(Bs[(cb + g)*GP + kk + q + 4]);
            }
            #pragma unroll
            for (int mt = 0; mt < 4; mt++)
                #pragma unroll
                for (int nt = 0; nt < 4; nt++)
                    mma16n8k8(acc[mt*4 + nt], af[mt], bf[nt]);
        }
        __syncthreads();
    }

    // epilogue
    #pragma unroll
    for (int mt = 0; mt < 4; mt++) {
        const int row0 = mBase + wm*64 + mt*16 + g;
        #pragma unroll
        for (int nt = 0; nt < 4; nt++) {
            const int col = nBase + wn*32 + nt*8 + 2*q;
            const float* a4 = acc[mt*4 + nt];
            float2 bv = *(const float2*)(bias + col);
            float o0 = a4[0] + bv.x, o1 = a4[1] + bv.y;
            float o2 = a4[2] + bv.x, o3 = a4[3] + bv.y;
            if (RESID) {
                float2 u = *(const float2*)(Rm + (size_t)row0*N + col);
                float2 v = *(const float2*)(Rm + (size_t)(row0+8)*N + col);
                o0 += u.x; o1 += u.y; o2 += v.x; o3 += v.y;
            }
            if (RELU) {
                o0 = fmaxf(o0, 0.f); o1 = fmaxf(o1, 0.f);
                o2 = fmaxf(o2, 0.f); o3 = fmaxf(o3, 0.f);
            }
            *(float2*)(C + (size_t)row0*N + col)     = make_float2(o0, o1);
            *(float2*)(C + (size_t)(row0+8)*N + col) = make_float2(o2, o3);
        }
    }
}

// ---------------- Flash attention v2 (tf32 mma, causal) ----------------
// block: 128 q-rows x 64 kv-cols per tile; 8 warps, warp owns 16 full q-rows.
// Q in registers, softmax in registers, P via warp-private smem (syncwarp only).
// K/V double-buffered via cp.async.
#define KP 68                       // K smem pitch
#define VP 72                       // V smem pitch (8q+g conflict-free)
#define PP 68                       // P smem pitch
#define KS_F (2*64*KP)              // 8704 floats
#define VS_F (2*64*VP)              // 9216 floats
#define P_F  (8*16*PP)              // 8704 floats
#define ATT_SMEM ((KS_F + VS_F + P_F) * 4)

__global__ __launch_bounds__(256, 1)
void attn_kernel(const float* __restrict__ qkv, float* __restrict__ out)
{
    extern __shared__ float sa[];
    float* Ksm = sa;
    float* Vsm = sa + KS_F;
    float* Psm = sa + KS_F + VS_F;

    const int tid = threadIdx.x;
    const int w = tid >> 5, lane = tid & 31;
    const int g = lane >> 2, q = lane & 3;
    const int qi = (gridDim.x - 1) - blockIdx.x;   // longest blocks first
    const int h = blockIdx.y, b = blockIdx.z;
    const int qBase = qi * 128;
    const size_t bT = (size_t)b * TT;

    float* Pw = Psm + w * 16 * PP;                 // warp-private [16][PP]

    // ---- stage Q tile (16 rows) through warp-private buffer into registers ----
    {
        const float* qg = qkv + (bT + qBase + w*16) * 3072 + h*64;
        #pragma unroll
        for (int i = 0; i < 8; i++) {
            int f = lane + i*32;
            int r = f >> 4, c4 = (f & 15) << 2;
            *(float4*)&Pw[r*PP + c4] = *(const float4*)(qg + (size_t)r*3072 + c4);
        }
    }
    __syncwarp();
    uint32_t qf[8][4];
    #pragma unroll
    for (int ks = 0; ks < 8; ks++) {
        const int kk = ks * 8;
        qf[ks][0] = cvt_rna(Pw[(g    )*PP + kk + q    ]);
        qf[ks][1] = cvt_rna(Pw[(g + 8)*PP + kk + q    ]);
        qf[ks][2] = cvt_rna(Pw[(g    )*PP + kk + q + 4]);
        qf[ks][3] = cvt_rna(Pw[(g + 8)*PP + kk + q + 4]);
    }
    __syncwarp();

    float m0 = NEG_INF, m1 = NEG_INF, l0 = 0.f, l1 = 0.f;
    float accO[8][4];
    #pragma unroll
    for (int i = 0; i < 8; i++)
        #pragma unroll
        for (int j = 0; j < 4; j++) accO[i][j] = 0.f;

    const int nT = 2*qi + 2;     // kv tiles 0..2qi+1
    const int lr = tid >> 4, lc4 = (tid & 15) << 2;   // K/V loader mapping (row, col4)

    // prologue: load kv tile 0 into stage 0
    {
        const float* kg = qkv + (bT + lr) * 3072 + EMB + h*64 + lc4;
        const uint32_t sk = s2u(Ksm) + (uint32_t)(lr*KP + lc4) * 4;
        const uint32_t sv = s2u(Vsm) + (uint32_t)(lr*VP + lc4) * 4;
        #pragma unroll
        for (int i = 0; i < 4; i++) {
            cpa16(sk + (uint32_t)(16*i*KP)*4, kg + (size_t)(16*i)*3072);
            cpa16(sv + (uint32_t)(16*i*VP)*4, kg + (size_t)(16*i)*3072 + EMB);
        }
        CP_COMMIT();
    }

    #pragma unroll 1
    for (int j = 0; j < nT; ++j) {
        if (j + 1 < nT) {
            const int st = (j + 1) & 1;
            const float* kg = qkv + (bT + (size_t)(j+1)*64 + lr) * 3072 + EMB + h*64 + lc4;
            const uint32_t sk = s2u(Ksm) + (uint32_t)((st*64 + lr)*KP + lc4) * 4;
            const uint32_t sv = s2u(Vsm) + (uint32_t)((st*64 + lr)*VP + lc4) * 4;
            #pragma unroll
            for (int i = 0; i < 4; i++) {
                cpa16(sk + (uint32_t)(16*i*KP)*4, kg + (size_t)(16*i)*3072);
                cpa16(sv + (uint32_t)(16*i*VP)*4, kg + (size_t)(16*i)*3072 + EMB);
            }
            CP_COMMIT();
            CP_WAIT(1);
        } else {
            CP_WAIT(0);
        }
        __syncthreads();

        const int jb = j * 64;
        const bool active = (jb <= qBase + w*16 + 15);
        if (active) {
            const float* Ks = Ksm + (j & 1) * 64 * KP;
            const float* Vs = Vsm + (j & 1) * 64 * VP;

            // ---- S = Q @ K^T : 8 n-tiles, 8 k-steps ----
            float sacc[8][4];
            #pragma unroll
            for (int i = 0; i < 8; i++)
                #pragma unroll
                for (int jj = 0; jj < 4; jj++) sacc[i][jj] = 0.f;

            #pragma unroll
            for (int ks = 0; ks < 8; ks++) {
                const int kk = ks * 8;
                uint32_t bf[8][2];
                #pragma unroll
                for (int nt = 0; nt < 8; nt++) {
                    bf[nt][0] = __float_as_uint(Ks[(nt*8 + g)*KP + kk + q    ]);
                    bf[nt][1] = __float_as_uint(Ks[(nt*8 + g)*KP + kk + q + 4]);
                }
                #pragma unroll
                for (int nt = 0; nt < 8; nt++)
                    mma16n8k8(sacc[nt], qf[ks], bf[nt]);
            }

            // scale + causal mask
            const int r0 = qBase + w*16 + g;
            const bool maskT = (jb + 63 > r0);  // any column may exceed row g (conservative per-thread)
            #pragma unroll
            for (int nt = 0; nt < 8; nt++) {
                sacc[nt][0] *= 0.125f; sacc[nt][1] *= 0.125f;
                sacc[nt][2] *= 0.125f; sacc[nt][3] *= 0.125f;
                if (maskT) {
                    const int c0 = jb + nt*8 + 2*q;
                    if (c0     > r0    ) sacc[nt][0] = NEG_INF;
                    if (c0 + 1 > r0    ) sacc[nt][1] = NEG_INF;
                    if (c0     > r0 + 8) sacc[nt][2] = NEG_INF;
                    if (c0 + 1 > r0 + 8) sacc[nt][3] = NEG_INF;
                }
            }

            // ---- online softmax in registers (rows g, g+8) ----
            float ml0 = NEG_INF, ml1 = NEG_INF;
            #pragma unroll
            for (int nt = 0; nt < 8; nt++) {
                ml0 = fmaxf(ml0, fmaxf(sacc[nt][0], sacc[nt][1]));
                ml1 = fmaxf(ml1, fmaxf(sacc[nt][2], sacc[nt][3]));
            }
            ml0 = fmaxf(ml0, __shfl_xor_sync(0xffffffffu, ml0, 1));
            ml0 = fmaxf(ml0, __shfl_xor_sync(0xffffffffu, ml0, 2));
            ml1 = fmaxf(ml1, __shfl_xor_sync(0xffffffffu, ml1, 1));
            ml1 = fmaxf(ml1, __shfl_xor_sync(0xffffffffu, ml1, 2));
            const float mn0 = fmaxf(m0, ml0);
            const float mn1 = fmaxf(m1, ml1);
            const float a0 = __expf(m0 - mn0);
            const float a1 = __expf(m1 - mn1);
            float s0 = 0.f, s1 = 0.f;
            #pragma unroll
            for (int nt = 0; nt < 8; nt++) {
                sacc[nt][0] = __expf(sacc[nt][0] - mn0);
                sacc[nt][1] = __expf(sacc[nt][1] - mn0);
                sacc[nt][2] = __expf(sacc[nt][2] - mn1);
                sacc[nt][3] = __expf(sacc[nt][3] - mn1);
                s0 += sacc[nt][0] + sacc[nt][1];
                s1 += sacc[nt][2] + sacc[nt][3];
            }
            s0 += __shfl_xor_sync(0xffffffffu, s0, 1);
            s0 += __shfl_xor_sync(0xffffffffu, s0, 2);
            s1 += __shfl_xor_sync(0xffffffffu, s1, 1);
            s1 += __shfl_xor_sync(0xffffffffu, s1, 2);
            m0 = mn0; m1 = mn1;
            l0 = l0 * a0 + s0;
            l1 = l1 * a1 + s1;
            #pragma unroll
            for (int dt = 0; dt < 8; dt++) {
                accO[dt][0] *= a0; accO[dt][1] *= a0;
                accO[dt][2] *= a1; accO[dt][3] *= a1;
            }

            // ---- P (rounded) -> warp-private smem ----
            #pragma unroll
            for (int nt = 0; nt < 8; nt++) {
                const int c = nt*8 + 2*q;
                *(float2*)&Pw[(g    )*PP + c] = make_float2(tf32r(sacc[nt][0]), tf32r(sacc[nt][1]));
                *(float2*)&Pw[(g + 8)*PP + c] = make_float2(tf32r(sacc[nt][2]), tf32r(sacc[nt][3]));
            }
            __syncwarp();

            // ---- O += P @ V ----
            #pragma unroll
            for (int ks = 0; ks < 8; ks++) {
                const int kk = ks * 8;
                uint32_t af[4];
                af[0] = __float_as_uint(Pw[(g    )*PP + kk + q    ]);
                af[1] = __float_as_uint(Pw[(g + 8)*PP + kk + q    ]);
                af[2] = __float_as_uint(Pw[(g    )*PP + kk + q + 4]);
                af[3] = __float_as_uint(Pw[(g + 8)*PP + kk + q + 4]);
                uint32_t bf[8][2];
                #pragma unroll
                for (int dt = 0; dt < 8; dt++) {
                    bf[dt][0] = __float_as_uint(Vs[(kk + q    )*VP + dt*8 + g]);
                    bf[dt][1] = __float_as_uint(Vs[(kk + q + 4)*VP + dt*8 + g]);
                }
                #pragma unroll
                for (int dt = 0; dt < 8; dt++)
                    mma16n8k8(accO[dt], af, bf[dt]);
            }
            __syncwarp();
        }
        __syncthreads();
    }

    // ---- finalize: divide by l, write out [b,t,e] ----
    const float inv0 = 1.f / l0;
    const float inv1 = 1.f / l1;
    const size_t row0 = bT + qBase + w*16 + g;
    #pragma unroll
    for (int dt = 0; dt < 8; dt++) {
        const int c = h*64 + dt*8 + 2*q;
        *(float2*)(out + row0*EMB + c)       = make_float2(accO[dt][0]*inv0, accO[dt][1]*inv0);
        *(float2*)(out + (row0 + 8)*EMB + c) = make_float2(accO[dt][2]*inv1, accO[dt][3]*inv1);
    }
}

// ---------------- LayerNorm over last dim (1024) ----------------
__global__ __launch_bounds__(256)
void ln_kernel(const float* __restrict__ in, const float* __restrict__ g,
               const float* __restrict__ bb, float* __restrict__ out)
{
    const int row = blockIdx.x, tid = threadIdx.x;
    const float* rp = in + (size_t)row * EMB;
    float4 v = *(const float4*)(rp + tid*4);
    float s  = v.x + v.y + v.z + v.w;
    float sq = v.x*v.x + v.y*v.y + v.z*v.z + v.w*v.w;
    #pragma unroll
    for (int o = 16; o > 0; o >>= 1) {
        s  += __shfl_xor_sync(0xffffffffu, s,  o);
        sq += __shfl_xor_sync(0xffffffffu, sq, o);
    }
    __shared__ float ws[8], wq[8], stat[2];
    const int w = tid >> 5;
    if ((tid & 31) == 0) { ws[w] = s; wq[w] = sq; }
    __syncthreads();
    if (tid == 0) {
        float ts = 0.f, tq = 0.f;
        #pragma unroll
        for (int i = 0; i < 8; i++) { ts += ws[i]; tq += wq[i]; }
        float mean = ts * (1.f/EMB);
        float var  = tq * (1.f/EMB) - mean*mean;
        stat[0] = mean;
        stat[1] = rsqrtf(var + 1e-5f);
    }
    __syncthreads();
    const float mean = stat[0], rs = stat[1];
    float4 gv = *(const float4*)(g  + tid*4);
    float4 bv = *(const float4*)(bb + tid*4);
    float4 o;
    o.x = (v.x - mean)*rs*gv.x + bv.x;
    o.y = (v.y - mean)*rs*gv.y + bv.y;
    o.z = (v.z - mean)*rs*gv.z + bv.z;
    o.w = (v.w - mean)*rs*gv.w + bv.w;
    *(float4*)(out + (size_t)row*EMB + tid*4) = o;
}

// ---------------- launch ----------------
extern "C" void kernel_launch(void* const* d_in, const int* in_sizes, int n_in,
                              void* d_out, int out_size)
{
    const float* x   = (const float*)d_in[0];
    const float* wat = (const float*)d_in[1];
    const float* bat = (const float*)d_in[2];
    const float* wpr = (const float*)d_in[3];
    const float* bpr = (const float*)d_in[4];
    const float* l1g = (const float*)d_in[5];
    const float* l1b = (const float*)d_in[6];
    const float* wf1 = (const float*)d_in[7];
    const float* bf1 = (const float*)d_in[8];
    const float* wf2 = (const float*)d_in[9];
    const float* bf2 = (const float*)d_in[10];
    const float* l2g = (const float*)d_in[11];
    const float* l2b = (const float*)d_in[12];

    static float *qkv = nullptr, *att, *res1, *x1, *ff, *res2, *watT, *wprT, *wf1T, *wf2T;
    if (!qkv) {
        cudaGetSymbolAddress((void**)&qkv,  g_qkv);
        cudaGetSymbolAddress((void**)&att,  g_att);
        cudaGetSymbolAddress((void**)&res1, g_res1);
        cudaGetSymbolAddress((void**)&x1,   g_x1);
        cudaGetSymbolAddress((void**)&ff,   g_ff);
        cudaGetSymbolAddress((void**)&res2, g_res2);
        cudaGetSymbolAddress((void**)&watT, g_watT);
        cudaGetSymbolAddress((void**)&wprT, g_wprT);
        cudaGetSymbolAddress((void**)&wf1T, g_wf1T);
        cudaGetSymbolAddress((void**)&wf2T, g_wf2T);
        cudaFuncSetAttribute(attn_kernel, cudaFuncAttributeMaxDynamicSharedMemorySize, ATT_SMEM);
        cudaFuncSetAttribute(gemm_mma<false,false>, cudaFuncAttributeMaxDynamicSharedMemorySize, GSMEM);
        cudaFuncSetAttribute(gemm_mma<false,true>,  cudaFuncAttributeMaxDynamicSharedMemorySize, GSMEM);
        cudaFuncSetAttribute(gemm_mma<true,false>,  cudaFuncAttributeMaxDynamicSharedMemorySize, GSMEM);
    }

    // weight transpose + tf32 rounding: [K,N] -> [N,K]
    transpose_cvt<<<dim3(3*EMB/32, EMB/32), dim3(32,8)>>>(wat, watT, EMB, 3*EMB);
    transpose_cvt<<<dim3(EMB/32,   EMB/32), dim3(32,8)>>>(wpr, wprT, EMB, EMB);
    transpose_cvt<<<dim3(DFF/32,   EMB/32), dim3(32,8)>>>(wf1, wf1T, EMB, DFF);
    transpose_cvt<<<dim3(EMB/32,   DFF/32), dim3(32,8)>>>(wf2, wf2T, DFF, EMB);

    // 1. QKV projection
    gemm_mma<false,false><<<dim3(3*EMB/128, MR/128), 256, GSMEM>>>(x, watT, bat, nullptr, qkv, 3*EMB, EMB);
    // 2. causal flash attention (128 q-rows per block)
    attn_kernel<<<dim3(TT/128, NH, BB), 256, ATT_SMEM>>>(qkv, att);
    // 3. output proj + residual(x)
    gemm_mma<false,true><<<dim3(EMB/128, MR/128), 256, GSMEM>>>(att, wprT, bpr, x, res1, EMB, EMB);
    // 4. LN1
    ln_kernel<<<MR, 256>>>(res1, l1g, l1b, x1);
    // 5. FF1 + ReLU
    gemm_mma<true,false><<<dim3(DFF/128, MR/128), 256, GSMEM>>>(x1, wf1T, bf1, nullptr, ff, DFF, EMB);
    // 6. FF2 + residual(x1)
    gemm_mma<false,true><<<dim3(EMB/128, MR/128), 256, GSMEM>>>(ff, wf2T, bf2, x1, res2, EMB, DFF);
    // 7. LN2 -> out
    ln_kernel<<<MR, 256>>>(res2, l2g, l2b, (float*)d_out);
}

// round 8
// speedup vs baseline: 3.6575x; 1.1008x over previous
#include <cuda_runtime.h>
#include <cstdint>

#define BB   4
#define TT   2048
#define EMB  1024
#define NH   16
#define DFF  4096
#define MR   (BB*TT)   // 8192 rows

#define NEG_INF (__int_as_float(0xff800000))

// ---------------- scratch (static device globals; no allocation) ----------------
__device__ float g_xr  [(size_t)MR * EMB];      // rounded x
__device__ float g_qkv [(size_t)MR * 3 * EMB];  // rounded
__device__ float g_att [(size_t)MR * EMB];      // rounded
__device__ float g_res1[(size_t)MR * EMB];
__device__ float g_x1f [(size_t)MR * EMB];      // unrounded (residual)
__device__ float g_x1r [(size_t)MR * EMB];      // rounded (GEMM A)
__device__ float g_ff  [(size_t)MR * DFF];      // rounded
__device__ float g_res2[(size_t)MR * EMB];
// transposed (tf32-rounded) weights: [N, K] row-major (K-major operand)
__device__ float g_watT[(size_t)3*EMB * EMB];
__device__ float g_wprT[(size_t)EMB * EMB];
__device__ float g_wf1T[(size_t)DFF * EMB];
__device__ float g_wf2T[(size_t)EMB * DFF];

// ================= helpers =================
static __device__ __forceinline__ uint32_t cvt_rna(float f) {
    uint32_t o;
    asm("cvt.rna.tf32.f32 %0, %1;" : "=r"(o) : "f"(f));
    return o;
}
static __device__ __forceinline__ float tf32r(float f) {
    return __uint_as_float(cvt_rna(f));
}
static __device__ __forceinline__ uint32_t s2u(const void* p) {
    uint32_t a;
    asm("{ .reg .u64 t; cvta.to.shared.u64 t, %1; cvt.u32.u64 %0, t; }" : "=r"(a) : "l"(p));
    return a;
}
static __device__ __forceinline__ void cpa16(uint32_t s, const void* g) {
    asm volatile("cp.async.cg.shared.global [%0], [%1], 16;" :: "r"(s), "l"(g));
}
#define CP_COMMIT() asm volatile("cp.async.commit_group;" ::: "memory")
#define CP_WAIT(n)  asm volatile("cp.async.wait_group %0;" :: "n"(n) : "memory")

static __device__ __forceinline__ void ldm_x4(uint32_t* r, uint32_t a) {
    asm volatile("ldmatrix.sync.aligned.m8n8.x4.shared.b16 {%0,%1,%2,%3}, [%4];"
        : "=r"(r[0]), "=r"(r[1]), "=r"(r[2]), "=r"(r[3]) : "r"(a));
}
static __device__ __forceinline__ void ldm_x2(uint32_t* r, uint32_t a) {
    asm volatile("ldmatrix.sync.aligned.m8n8.x2.shared.b16 {%0,%1}, [%2];"
        : "=r"(r[0]), "=r"(r[1]) : "r"(a));
}
// D += A@B  (m16n8k8, tf32 inputs as b32, fp32 accum)
static __device__ __forceinline__ void mma16n8k8(float* d, const uint32_t* a, const uint32_t* b) {
    asm volatile(
        "mma.sync.aligned.m16n8k8.row.col.f32.tf32.tf32.f32 "
        "{%0,%1,%2,%3}, {%4,%5,%6,%7}, {%8,%9}, {%0,%1,%2,%3};"
        : "+f"(d[0]), "+f"(d[1]), "+f"(d[2]), "+f"(d[3])
        : "r"(a[0]), "r"(a[1]), "r"(a[2]), "r"(a[3]), "r"(b[0]), "r"(b[1]));
}

// ================= elementwise tf32 round =================
__global__ __launch_bounds__(256)
void round_copy(const float4* __restrict__ in, float4* __restrict__ out)
{
    size_t i = (size_t)blockIdx.x * 256 + threadIdx.x;
    float4 v = in[i];
    out[i] = make_float4(tf32r(v.x), tf32r(v.y), tf32r(v.z), tf32r(v.w));
}

// ================= weight transpose + tf32 round =================
__global__ __launch_bounds__(256)
void transpose_cvt(const float* __restrict__ in, float* __restrict__ out, int K, int N)
{
    __shared__ float t[32][33];
    const int n0 = blockIdx.x * 32, k0 = blockIdx.y * 32;
    const int tx = threadIdx.x, ty = threadIdx.y;
    #pragma unroll
    for (int i = 0; i < 32; i += 8)
        t[ty + i][tx] = in[(size_t)(k0 + ty + i) * N + n0 + tx];
    __syncthreads();
    #pragma unroll
    for (int i = 0; i < 32; i += 8)
        out[(size_t)(n0 + ty + i) * K + k0 + tx] = tf32r(t[tx][ty + i]);
}

// ================= tf32 mma GEMM, cp.async 3-stage, ldmatrix fragments =================
// C[M,N] = A[M,K] @ Bt[N,K]^T + bias (+resid)(+relu)(+round)
// block 128x128, BK=32, 256 thr, warp grid 2(m) x 4(n), warp tile 64x32.
#define GP      36
#define GTILE   (128*GP)            // floats per stage per operand
#define GSMEM   (6*GTILE*4)         // 3 stages x (A,B)

template<bool RELU, bool RESID, bool ROUND>
__global__ __launch_bounds__(256, 2)
void gemm_mma(const float* __restrict__ A, const float* __restrict__ Bt,
              const float* __restrict__ bias, const float* __restrict__ Rm,
              float* __restrict__ C, int N, int K)
{
    extern __shared__ float sg[];
    float* Asm = sg;                // [3][128][GP]
    float* Bsm = sg + 3*GTILE;      // [3][128][GP]

    const int tid = threadIdx.x;
    const int wid = tid >> 5, lane = tid & 31;
    const int wm = wid >> 2, wn = wid & 3;
    const int g = lane >> 2, q = lane & 3;
    const int Lt = lane >> 3, Lr = lane & 7;
    const int mBase = blockIdx.y << 7, nBase = blockIdx.x << 7;
    const int lrow = tid >> 3, lc4 = (tid & 7) << 2;

    const float* ap = A  + (size_t)(mBase + lrow) * K + lc4;
    const float* bp = Bt + (size_t)(nBase + lrow) * K + lc4;
    const uint32_t sAld = s2u(Asm) + (uint32_t)(lrow*GP + lc4) * 4;
    const uint32_t sBld = s2u(Bsm) + (uint32_t)(lrow*GP + lc4) * 4;

    // ldmatrix lane bases
    uint32_t aAddr[4], bAddr[4];
    #pragma unroll
    for (int mt = 0; mt < 4; mt++) {
        const int row = wm*64 + mt*16 + (Lt & 1)*8 + Lr;
        aAddr[mt] = s2u(Asm) + (uint32_t)((row*GP + (Lt >> 1)*4) * 4);
    }
    #pragma unroll
    for (int nt = 0; nt < 4; nt++) {
        const int row = wn*32 + nt*8 + Lr;
        bAddr[nt] = s2u(Bsm) + (uint32_t)((row*GP + (Lt & 1)*4) * 4);
    }

    float acc[16][4];
    #pragma unroll
    for (int i = 0; i < 16; i++)
        #pragma unroll
        for (int j = 0; j < 4; j++) acc[i][j] = 0.f;

    const int nT = K >> 5;

    // prologue: stages 0 and 1
    #pragma unroll
    for (int s = 0; s < 2; s++) {
        const uint32_t so = (uint32_t)(s * GTILE) * 4;
        const size_t kof = (size_t)s * 32;
        #pragma unroll
        for (int i = 0; i < 4; i++) {
            cpa16(sAld + so + (uint32_t)(32*i*GP)*4, ap + (size_t)(32*i)*K + kof);
            cpa16(sBld + so + (uint32_t)(32*i*GP)*4, bp + (size_t)(32*i)*K + kof);
        }
        CP_COMMIT();
    }

    #pragma unroll 1
    for (int t = 0; t < nT; ++t) {
        if (t + 1 < nT) { CP_WAIT(1); } else { CP_WAIT(0); }
        __syncthreads();

        if (t + 2 < nT) {
            const int st = (t + 2) % 3;
            const uint32_t so = (uint32_t)(st * GTILE) * 4;
            const size_t kof = (size_t)(t + 2) * 32;
            #pragma unroll
            for (int i = 0; i < 4; i++) {
                cpa16(sAld + so + (uint32_t)(32*i*GP)*4, ap + (size_t)(32*i)*K + kof);
                cpa16(sBld + so + (uint32_t)(32*i*GP)*4, bp + (size_t)(32*i)*K + kof);
            }
            CP_COMMIT();
        }

        const uint32_t so = (uint32_t)((t % 3) * GTILE) * 4;
        #pragma unroll
        for (int ks = 0; ks < 4; ks++) {
            const uint32_t kk4 = (uint32_t)(ks * 8 * 4);
            uint32_t af[4][4], bf[4][2];
            #pragma unroll
            for (int mt = 0; mt < 4; mt++) ldm_x4(af[mt], aAddr[mt] + so + kk4);
            #pragma unroll
            for (int nt = 0; nt < 4; nt++) ldm_x2(bf[nt], bAddr[nt] + so + kk4);
            #pragma unroll
            for (int mt = 0; mt < 4; mt++)
                #pragma unroll
                for (int nt = 0; nt < 4; nt++)
                    mma16n8k8(acc[mt*4 + nt], af[mt], bf[nt]);
        }
    }

    // epilogue
    #pragma unroll
    for (int mt = 0; mt < 4; mt++) {
        const int row0 = mBase + wm*64 + mt*16 + g;
        #pragma unroll
        for (int nt = 0; nt < 4; nt++) {
            const int col = nBase + wn*32 + nt*8 + 2*q;
            const float* a4 = acc[mt*4 + nt];
            float2 bv = *(const float2*)(bias + col);
            float o0 = a4[0] + bv.x, o1 = a4[1] + bv.y;
            float o2 = a4[2] + bv.x, o3 = a4[3] + bv.y;
            if (RESID) {
                float2 u = *(const float2*)(Rm + (size_t)row0*N + col);
                float2 v = *(const float2*)(Rm + (size_t)(row0+8)*N + col);
                o0 += u.x; o1 += u.y; o2 += v.x; o3 += v.y;
            }
            if (RELU) {
                o0 = fmaxf(o0, 0.f); o1 = fmaxf(o1, 0.f);
                o2 = fmaxf(o2, 0.f); o3 = fmaxf(o3, 0.f);
            }
            if (ROUND) {
                o0 = tf32r(o0); o1 = tf32r(o1); o2 = tf32r(o2); o3 = tf32r(o3);
            }
            *(float2*)(C + (size_t)row0*N + col)     = make_float2(o0, o1);
            *(float2*)(C + (size_t)(row0+8)*N + col) = make_float2(o2, o3);
        }
    }
}

// ---------------- Flash attention v2 (tf32 mma, causal) ----------------
// 64 q-rows x 64 kv-cols tiles; 4 warps (128 thr), warp owns 16 q-rows.
// Q/K/P fragments via ldmatrix; softmax in registers; occupancy 2.
#define KP 68
#define VP 68
#define PP 68
#define ATT_SMEM ((2*64*KP + 2*64*VP + 4*16*PP + 4*16*PP) * 4)

__global__ __launch_bounds__(128, 2)
void attn_kernel(const float* __restrict__ qkv, float* __restrict__ out)
{
    extern __shared__ float sa[];
    float* Ksm = sa;                    // [2][64][KP]
    float* Vsm = Ksm + 2*64*KP;         // [2][64][VP]
    float* Psm = Vsm + 2*64*VP;         // [4][16][PP]
    float* Qsm = Psm + 4*16*PP;         // [4][16][PP]

    const int tid = threadIdx.x;
    const int w = tid >> 5, lane = tid & 31;
    const int g = lane >> 2, q = lane & 3;
    const int Lt = lane >> 3, Lr = lane & 7;
    const int qi = (gridDim.x - 1) - blockIdx.x;   // longest first
    const int h = blockIdx.y, b = blockIdx.z;
    const int qBase = qi * 64;
    const size_t bT = (size_t)b * TT;

    float* Pw = Psm + w*16*PP;
    float* Qw = Qsm + w*16*PP;

    // load Q tile (pre-rounded qkv)
    {
        const float* qg = qkv + (bT + qBase + w*16) * 3072 + h*64;
        #pragma unroll
        for (int i = 0; i < 8; i++) {
            int f = lane + i*32;
            int r = f >> 4, c4 = (f & 15) << 2;
            *(float4*)&Qw[r*PP + c4] = *(const float4*)(qg + (size_t)r*3072 + c4);
        }
    }
    __syncwarp();

    float m0 = NEG_INF, m1 = NEG_INF, l0 = 0.f, l1 = 0.f;
    float accO[8][4];
    #pragma unroll
    for (int i = 0; i < 8; i++)
        #pragma unroll
        for (int j = 0; j < 4; j++) accO[i][j] = 0.f;

    const int nT = qi + 1;
    const uint32_t skb = s2u(Ksm), svb = s2u(Vsm);
    const uint32_t lmq = s2u(Qw) + (uint32_t)(((((Lt & 1)*8) + Lr)*PP + (Lt >> 1)*4) * 4);
    const uint32_t lmp = s2u(Pw) + (uint32_t)(((((Lt & 1)*8) + Lr)*PP + (Lt >> 1)*4) * 4);
    const uint32_t lmk = skb + (uint32_t)((Lr*KP + (Lt & 1)*4) * 4);

    // prologue: kv tile 0 -> stage 0
    {
        const float* kg = qkv + bT * 3072 + EMB + h*64;
        #pragma unroll
        for (int i = 0; i < 8; i++) {
            int f = tid + i*128;
            int r = f >> 4, c4 = (f & 15) << 2;
            cpa16(skb + (uint32_t)((r*KP + c4)*4), kg + (size_t)r*3072 + c4);
            cpa16(svb + (uint32_t)((r*VP + c4)*4), kg + (size_t)r*3072 + EMB + c4);
        }
        CP_COMMIT();
    }

    #pragma unroll 1
    for (int j = 0; j < nT; ++j) {
        if (j + 1 < nT) {
            const int st = (j + 1) & 1;
            const float* kg = qkv + (bT + (size_t)(j+1)*64) * 3072 + EMB + h*64;
            #pragma unroll
            for (int i = 0; i < 8; i++) {
                int f = tid + i*128;
                int r = f >> 4, c4 = (f & 15) << 2;
                cpa16(skb + (uint32_t)(((st*64 + r)*KP + c4)*4), kg + (size_t)r*3072 + c4);
                cpa16(svb + (uint32_t)(((st*64 + r)*VP + c4)*4), kg + (size_t)r*3072 + EMB + c4);
            }
            CP_COMMIT();
            CP_WAIT(1);
        } else {
            CP_WAIT(0);
        }
        __syncthreads();

        const uint32_t kst = (uint32_t)((j & 1) * 64 * KP * 4);
        const float* Vs = Vsm + (j & 1) * 64 * VP;

        // ---- S = Q @ K^T ----
        float sacc[8][4];
        #pragma unroll
        for (int i = 0; i < 8; i++)
            #pragma unroll
            for (int jj = 0; jj < 4; jj++) sacc[i][jj] = 0.f;

        #pragma unroll
        for (int ks = 0; ks < 8; ks++) {
            const uint32_t kk4 = (uint32_t)(ks * 8 * 4);
            uint32_t aq[4];
            ldm_x4(aq, lmq + kk4);
            uint32_t bf[8][2];
            #pragma unroll
            for (int nt = 0; nt < 8; nt++)
                ldm_x2(bf[nt], lmk + kst + (uint32_t)(nt*8*KP*4) + kk4);
            #pragma unroll
            for (int nt = 0; nt < 8; nt++)
                mma16n8k8(sacc[nt], aq, bf[nt]);
        }

        // scale + causal mask (only diag tile)
        const int r0 = qBase + w*16 + g;
        const int jb = j * 64;
        const bool diag = (j == qi);
        #pragma unroll
        for (int nt = 0; nt < 8; nt++) {
            sacc[nt][0] *= 0.125f; sacc[nt][1] *= 0.125f;
            sacc[nt][2] *= 0.125f; sacc[nt][3] *= 0.125f;
            if (diag) {
                const int c0 = jb + nt*8 + 2*q;
                if (c0     > r0    ) sacc[nt][0] = NEG_INF;
                if (c0 + 1 > r0    ) sacc[nt][1] = NEG_INF;
                if (c0     > r0 + 8) sacc[nt][2] = NEG_INF;
                if (c0 + 1 > r0 + 8) sacc[nt][3] = NEG_INF;
            }
        }

        // ---- online softmax in registers ----
        float ml0 = NEG_INF, ml1 = NEG_INF;
        #pragma unroll
        for (int nt = 0; nt < 8; nt++) {
            ml0 = fmaxf(ml0, fmaxf(sacc[nt][0], sacc[nt][1]));
            ml1 = fmaxf(ml1, fmaxf(sacc[nt][2], sacc[nt][3]));
        }
        ml0 = fmaxf(ml0, __shfl_xor_sync(0xffffffffu, ml0, 1));
        ml0 = fmaxf(ml0, __shfl_xor_sync(0xffffffffu, ml0, 2));
        ml1 = fmaxf(ml1, __shfl_xor_sync(0xffffffffu, ml1, 1));
        ml1 = fmaxf(ml1, __shfl_xor_sync(0xffffffffu, ml1, 2));
        const float mn0 = fmaxf(m0, ml0);
        const float mn1 = fmaxf(m1, ml1);
        const float a0 = __expf(m0 - mn0);
        const float a1 = __expf(m1 - mn1);
        float s0 = 0.f, s1 = 0.f;
        #pragma unroll
        for (int nt = 0; nt < 8; nt++) {
            sacc[nt][0] = __expf(sacc[nt][0] - mn0);
            sacc[nt][1] = __expf(sacc[nt][1] - mn0);
            sacc[nt][2] = __expf(sacc[nt][2] - mn1);
            sacc[nt][3] = __expf(sacc[nt][3] - mn1);
            s0 += sacc[nt][0] + sacc[nt][1];
            s1 += sacc[nt][2] + sacc[nt][3];
        }
        s0 += __shfl_xor_sync(0xffffffffu, s0, 1);
        s0 += __shfl_xor_sync(0xffffffffu, s0, 2);
        s1 += __shfl_xor_sync(0xffffffffu, s1, 1);
        s1 += __shfl_xor_sync(0xffffffffu, s1, 2);
        m0 = mn0; m1 = mn1;
        l0 = l0 * a0 + s0;
        l1 = l1 * a1 + s1;
        #pragma unroll
        for (int dt = 0; dt < 8; dt++) {
            accO[dt][0] *= a0; accO[dt][1] *= a0;
            accO[dt][2] *= a1; accO[dt][3] *= a1;
        }

        // ---- P (rounded) -> warp-private smem ----
        #pragma unroll
        for (int nt = 0; nt < 8; nt++) {
            const int c = nt*8 + 2*q;
            *(float2*)&Pw[(g    )*PP + c] = make_float2(tf32r(sacc[nt][0]), tf32r(sacc[nt][1]));
            *(float2*)&Pw[(g + 8)*PP + c] = make_float2(tf32r(sacc[nt][2]), tf32r(sacc[nt][3]));
        }
        __syncwarp();

        // ---- O += P @ V ----
        #pragma unroll
        for (int ks = 0; ks < 8; ks++) {
            const int kk = ks * 8;
            uint32_t af[4];
            ldm_x4(af, lmp + (uint32_t)(kk*4));
            uint32_t bf[8][2];
            #pragma unroll
            for (int dt = 0; dt < 8; dt++) {
                bf[dt][0] = __float_as_uint(Vs[(kk + q    )*VP + dt*8 + g]);
                bf[dt][1] = __float_as_uint(Vs[(kk + q + 4)*VP + dt*8 + g]);
            }
            #pragma unroll
            for (int dt = 0; dt < 8; dt++)
                mma16n8k8(accO[dt], af, bf[dt]);
        }
        __syncwarp();
        __syncthreads();
    }

    // ---- finalize: divide by l, round, write out [b,t,e] ----
    const float inv0 = 1.f / l0;
    const float inv1 = 1.f / l1;
    const size_t row0 = bT + qBase + w*16 + g;
    #pragma unroll
    for (int dt = 0; dt < 8; dt++) {
        const int c = h*64 + dt*8 + 2*q;
        *(float2*)(out + row0*EMB + c) =
            make_float2(tf32r(accO[dt][0]*inv0), tf32r(accO[dt][1]*inv0));
        *(float2*)(out + (row0 + 8)*EMB + c) =
            make_float2(tf32r(accO[dt][2]*inv1), tf32r(accO[dt][3]*inv1));
    }
}

// ---------------- LayerNorm over last dim (1024) ----------------
// writes fp32 out; optionally also tf32-rounded copy
__global__ __launch_bounds__(256)
void ln_kernel(const float* __restrict__ in, const float* __restrict__ g,
               const float* __restrict__ bb, float* __restrict__ out,
               float* __restrict__ outr)
{
    const int row = blockIdx.x, tid = threadIdx.x;
    const float* rp = in + (size_t)row * EMB;
    float4 v = *(const float4*)(rp + tid*4);
    float s  = v.x + v.y + v.z + v.w;
    float sq = v.x*v.x + v.y*v.y + v.z*v.z + v.w*v.w;
    #pragma unroll
    for (int o = 16; o > 0; o >>= 1) {
        s  += __shfl_xor_sync(0xffffffffu, s,  o);
        sq += __shfl_xor_sync(0xffffffffu, sq, o);
    }
    __shared__ float ws[8], wq[8], stat[2];
    const int w = tid >> 5;
    if ((tid & 31) == 0) { ws[w] = s; wq[w] = sq; }
    __syncthreads();
    if (tid == 0) {
        float ts = 0.f, tq = 0.f;
        #pragma unroll
        for (int i = 0; i < 8; i++) { ts += ws[i]; tq += wq[i]; }
        float mean = ts * (1.f/EMB);
        float var  = tq * (1.f/EMB) - mean*mean;
        stat[0] = mean;
        stat[1] = rsqrtf(var + 1e-5f);
    }
    __syncthreads();
    const float mean = stat[0], rs = stat[1];
    float4 gv = *(const float4*)(g  + tid*4);
    float4 bv = *(const float4*)(bb + tid*4);
    float4 o;
    o.x = (v.x - mean)*rs*gv.x + bv.x;
    o.y = (v.y - mean)*rs*gv.y + bv.y;
    o.z = (v.z - mean)*rs*gv.z + bv.z;
    o.w = (v.w - mean)*rs*gv.w + bv.w;
    *(float4*)(out + (size_t)row*EMB + tid*4) = o;
    if (outr) {
        *(float4*)(outr + (size_t)row*EMB + tid*4) =
            make_float4(tf32r(o.x), tf32r(o.y), tf32r(o.z), tf32r(o.w));
    }
}

// ---------------- launch ----------------
extern "C" void kernel_launch(void* const* d_in, const int* in_sizes, int n_in,
                              void* d_out, int out_size)
{
    const float* x   = (const float*)d_in[0];
    const float* wat = (const float*)d_in[1];
    const float* bat = (const float*)d_in[2];
    const float* wpr = (const float*)d_in[3];
    const float* bpr = (const float*)d_in[4];
    const float* l1g = (const float*)d_in[5];
    const float* l1b = (const float*)d_in[6];
    const float* wf1 = (const float*)d_in[7];
    const float* bf1 = (const float*)d_in[8];
    const float* wf2 = (const float*)d_in[9];
    const float* bf2 = (const float*)d_in[10];
    const float* l2g = (const float*)d_in[11];
    const float* l2b = (const float*)d_in[12];

    static float *xr = nullptr, *qkv, *att, *res1, *x1f, *x1r, *ff, *res2,
                 *watT, *wprT, *wf1T, *wf2T;
    if (!xr) {
        cudaGetSymbolAddress((void**)&xr,   g_xr);
        cudaGetSymbolAddress((void**)&qkv,  g_qkv);
        cudaGetSymbolAddress((void**)&att,  g_att);
        cudaGetSymbolAddress((void**)&res1, g_res1);
        cudaGetSymbolAddress((void**)&x1f,  g_x1f);
        cudaGetSymbolAddress((void**)&x1r,  g_x1r);
        cudaGetSymbolAddress((void**)&ff,   g_ff);
        cudaGetSymbolAddress((void**)&res2, g_res2);
        cudaGetSymbolAddress((void**)&watT, g_watT);
        cudaGetSymbolAddress((void**)&wprT, g_wprT);
        cudaGetSymbolAddress((void**)&wf1T, g_wf1T);
        cudaGetSymbolAddress((void**)&wf2T, g_wf2T);
        cudaFuncSetAttribute(attn_kernel, cudaFuncAttributeMaxDynamicSharedMemorySize, ATT_SMEM);
        cudaFuncSetAttribute(gemm_mma<false,false,true>,  cudaFuncAttributeMaxDynamicSharedMemorySize, GSMEM);
        cudaFuncSetAttribute(gemm_mma<false,true,false>,  cudaFuncAttributeMaxDynamicSharedMemorySize, GSMEM);
        cudaFuncSetAttribute(gemm_mma<true,false,true>,   cudaFuncAttributeMaxDynamicSharedMemorySize, GSMEM);
    }

    // pre-round x; transpose + round weights
    round_copy<<<MR*EMB/1024, 256>>>((const float4*)x, (float4*)xr);
    transpose_cvt<<<dim3(3*EMB/32, EMB/32), dim3(32,8)>>>(wat, watT, EMB, 3*EMB);
    transpose_cvt<<<dim3(EMB/32,   EMB/32), dim3(32,8)>>>(wpr, wprT, EMB, EMB);
    transpose_cvt<<<dim3(DFF/32,   EMB/32), dim3(32,8)>>>(wf1, wf1T, EMB, DFF);
    transpose_cvt<<<dim3(EMB/32,   DFF/32), dim3(32,8)>>>(wf2, wf2T, DFF, EMB);

    // 1. QKV projection (output rounded)
    gemm_mma<false,false,true><<<dim3(3*EMB/128, MR/128), 256, GSMEM>>>(xr, watT, bat, nullptr, qkv, 3*EMB, EMB);
    // 2. causal flash attention (output rounded)
    attn_kernel<<<dim3(TT/64, NH, BB), 128, ATT_SMEM>>>(qkv, att);
    // 3. output proj + residual(x)
    gemm_mma<false,true,false><<<dim3(EMB/128, MR/128), 256, GSMEM>>>(att, wprT, bpr, x, res1, EMB, EMB);
    // 4. LN1 -> x1f (fp32) + x1r (rounded)
    ln_kernel<<<MR, 256>>>(res1, l1g, l1b, x1f, x1r);
    // 5. FF1 + ReLU (output rounded)
    gemm_mma<true,false,true><<<dim3(DFF/128, MR/128), 256, GSMEM>>>(x1r, wf1T, bf1, nullptr, ff, DFF, EMB);
    // 6. FF2 + residual(x1f)
    gemm_mma<false,true,false><<<dim3(EMB/128, MR/128), 256, GSMEM>>>(ff, wf2T, bf2, x1f, res2, EMB, DFF);
    // 7. LN2 -> out
    ln_kernel<<<MR, 256>>>(res2, l2g, l2b, (float*)d_out, nullptr);
}

// round 9
// speedup vs baseline: 5.7720x; 1.5781x over previous
#include <cuda_runtime.h>
#include <cuda_fp16.h>
#include <cstdint>

#define BB   4
#define TT   2048
#define EMB  1024
#define NH   16
#define DFF  4096
#define MR   (BB*TT)   // 8192 rows

#define NEG_INF (__int_as_float(0xff800000))

// ---------------- scratch (static device globals; no allocation) ----------------
__device__ __half g_xh  [(size_t)MR * EMB];       // half x (GEMM A)
__device__ __half g_qkvh[(size_t)MR * 3 * EMB];   // half qkv
__device__ __half g_atth[(size_t)MR * EMB];       // half attention out
__device__ float  g_res1[(size_t)MR * EMB];
__device__ float  g_x1f [(size_t)MR * EMB];       // fp32 (residual)
__device__ __half g_x1h [(size_t)MR * EMB];       // half (GEMM A)
__device__ __half g_ffh [(size_t)MR * DFF];       // half ff
__device__ float  g_res2[(size_t)MR * EMB];
// transposed half weights: [N, K] row-major (K-major operand)
__device__ __half g_watT[(size_t)3*EMB * EMB];
__device__ __half g_wprT[(size_t)EMB * EMB];
__device__ __half g_wf1T[(size_t)DFF * EMB];
__device__ __half g_wf2T[(size_t)EMB * DFF];

// ================= helpers =================
static __device__ __forceinline__ uint32_t s2u(const void* p) {
    uint32_t a;
    asm("{ .reg .u64 t; cvta.to.shared.u64 t, %1; cvt.u32.u64 %0, t; }" : "=r"(a) : "l"(p));
    return a;
}
static __device__ __forceinline__ void cpa16(uint32_t s, const void* g) {
    asm volatile("cp.async.cg.shared.global [%0], [%1], 16;" :: "r"(s), "l"(g));
}
#define CP_COMMIT() asm volatile("cp.async.commit_group;" ::: "memory")
#define CP_WAIT(n)  asm volatile("cp.async.wait_group %0;" :: "n"(n) : "memory")

static __device__ __forceinline__ void ldm_x4(uint32_t* r, uint32_t a) {
    asm volatile("ldmatrix.sync.aligned.m8n8.x4.shared.b16 {%0,%1,%2,%3}, [%4];"
        : "=r"(r[0]), "=r"(r[1]), "=r"(r[2]), "=r"(r[3]) : "r"(a));
}
static __device__ __forceinline__ void ldm_x2(uint32_t* r, uint32_t a) {
    asm volatile("ldmatrix.sync.aligned.m8n8.x2.shared.b16 {%0,%1}, [%2];"
        : "=r"(r[0]), "=r"(r[1]) : "r"(a));
}
static __device__ __forceinline__ void ldm_x2_t(uint32_t* r, uint32_t a) {
    asm volatile("ldmatrix.sync.aligned.m8n8.x2.trans.shared.b16 {%0,%1}, [%2];"
        : "=r"(r[0]), "=r"(r[1]) : "r"(a));
}
// D += A@B  (m16n8k16, fp16 inputs, fp32 accum)
static __device__ __forceinline__ void mma_f16(float* d, const uint32_t* a, const uint32_t* b) {
    asm volatile(
        "mma.sync.aligned.m16n8k16.row.col.f32.f16.f16.f32 "
        "{%0,%1,%2,%3}, {%4,%5,%6,%7}, {%8,%9}, {%0,%1,%2,%3};"
        : "+f"(d[0]), "+f"(d[1]), "+f"(d[2]), "+f"(d[3])
        : "r"(a[0]), "r"(a[1]), "r"(a[2]), "r"(a[3]), "r"(b[0]), "r"(b[1]));
}
static __device__ __forceinline__ uint32_t pack_h2(float a, float b) {
    __half2 h = __floats2half2_rn(a, b);
    return *(uint32_t*)&h;
}

// ================= x -> half =================
__global__ __launch_bounds__(256)
void cvt_half(const float4* __restrict__ in, uint2* __restrict__ out)
{
    size_t i = (size_t)blockIdx.x * 256 + threadIdx.x;
    float4 v = in[i];
    out[i] = make_uint2(pack_h2(v.x, v.y), pack_h2(v.z, v.w));
}

// ================= weight transpose -> half =================
__global__ __launch_bounds__(256)
void transpose_cvt(const float* __restrict__ in, __half* __restrict__ out, int K, int N)
{
    __shared__ float t[32][33];
    const int n0 = blockIdx.x * 32, k0 = blockIdx.y * 32;
    const int tx = threadIdx.x, ty = threadIdx.y;
    #pragma unroll
    for (int i = 0; i < 32; i += 8)
        t[ty + i][tx] = in[(size_t)(k0 + ty + i) * N + n0 + tx];
    __syncthreads();
    #pragma unroll
    for (int i = 0; i < 32; i += 8)
        out[(size_t)(n0 + ty + i) * K + k0 + tx] = __float2half_rn(t[tx][ty + i]);
}

// ================= fp16 mma GEMM, cp.async 3-stage, ldmatrix =================
// C = A[M,K] @ Bt[N,K]^T + bias (+resid)(+relu); out fp32 or fp16.
// block 128x128, BK=32 halves, 256 thr, warp grid 2x4, warp tile 64x32.
#define GPH     40                    // smem pitch (halves) = 80 B (16B-aligned, cf-free)
#define GTILEH  (128*GPH)             // halves per stage per operand
#define GSMEM   (6*GTILEH*2)          // bytes: 3 stages x (A,B)

template<bool RELU, bool RESID, bool HOUT>
__global__ __launch_bounds__(256, 2)
void gemm_mma(const __half* __restrict__ A, const __half* __restrict__ Bt,
              const float* __restrict__ bias, const float* __restrict__ Rm,
              float* __restrict__ Cf, __half* __restrict__ Ch, int N, int K)
{
    extern __shared__ __half sh[];
    __half* Asm = sh;                 // [3][128][GPH]
    __half* Bsm = sh + 3*GTILEH;

    const int tid = threadIdx.x;
    const int wid = tid >> 5, lane = tid & 31;
    const int wm = wid >> 2, wn = wid & 3;
    const int g = lane >> 2, q = lane & 3;
    const int Lt = lane >> 3, Lr = lane & 7;
    const int mBase = blockIdx.y << 7, nBase = blockIdx.x << 7;
    const int lrow = tid >> 1, lcH = (tid & 1) << 4;   // 2 threads/row, 16-half halves

    const __half* ap = A  + (size_t)(mBase + lrow) * K + lcH;
    const __half* bp = Bt + (size_t)(nBase + lrow) * K + lcH;
    const uint32_t sAld = s2u(Asm) + (uint32_t)(lrow*GPH + lcH) * 2;
    const uint32_t sBld = s2u(Bsm) + (uint32_t)(lrow*GPH + lcH) * 2;

    // ldmatrix lane bases
    uint32_t aAddr[4], bAddr[4];
    #pragma unroll
    for (int mt = 0; mt < 4; mt++) {
        const int row = wm*64 + mt*16 + (Lt & 1)*8 + Lr;
        aAddr[mt] = s2u(Asm) + (uint32_t)((row*GPH + (Lt >> 1)*8) * 2);
    }
    #pragma unroll
    for (int nt = 0; nt < 4; nt++) {
        const int row = wn*32 + nt*8 + Lr;
        bAddr[nt] = s2u(Bsm) + (uint32_t)((row*GPH + (Lt & 1)*8) * 2);
    }

    float acc[16][4];
    #pragma unroll
    for (int i = 0; i < 16; i++)
        #pragma unroll
        for (int j = 0; j < 4; j++) acc[i][j] = 0.f;

    const int nT = K >> 5;

    #pragma unroll
    for (int s = 0; s < 2; s++) {
        const uint32_t so = (uint32_t)(s * GTILEH) * 2;
        const size_t kof = (size_t)s * 32;
        cpa16(sAld + so,      ap + kof);
        cpa16(sAld + so + 16, ap + kof + 8);
        cpa16(sBld + so,      bp + kof);
        cpa16(sBld + so + 16, bp + kof + 8);
        CP_COMMIT();
    }

    #pragma unroll 1
    for (int t = 0; t < nT; ++t) {
        if (t + 1 < nT) { CP_WAIT(1); } else { CP_WAIT(0); }
        __syncthreads();

        if (t + 2 < nT) {
            const int st = (t + 2) % 3;
            const uint32_t so = (uint32_t)(st * GTILEH) * 2;
            const size_t kof = (size_t)(t + 2) * 32;
            cpa16(sAld + so,      ap + kof);
            cpa16(sAld + so + 16, ap + kof + 8);
            cpa16(sBld + so,      bp + kof);
            cpa16(sBld + so + 16, bp + kof + 8);
            CP_COMMIT();
        }

        const uint32_t so = (uint32_t)((t % 3) * GTILEH) * 2;
        #pragma unroll
        for (int ks = 0; ks < 2; ks++) {          // two k16 steps per BK=32
            const uint32_t kb = (uint32_t)(ks * 32);   // 16 halves = 32 B
            uint32_t af[4][4], bf[4][2];
            #pragma unroll
            for (int mt = 0; mt < 4; mt++) ldm_x4(af[mt], aAddr[mt] + so + kb);
            #pragma unroll
            for (int nt = 0; nt < 4; nt++) ldm_x2(bf[nt], bAddr[nt] + so + kb);
            #pragma unroll
            for (int mt = 0; mt < 4; mt++)
                #pragma unroll
                for (int nt = 0; nt < 4; nt++)
                    mma_f16(acc[mt*4 + nt], af[mt], bf[nt]);
        }
    }

    // epilogue
    #pragma unroll
    for (int mt = 0; mt < 4; mt++) {
        const int row0 = mBase + wm*64 + mt*16 + g;
        #pragma unroll
        for (int nt = 0; nt < 4; nt++) {
            const int col = nBase + wn*32 + nt*8 + 2*q;
            const float* a4 = acc[mt*4 + nt];
            float2 bv = *(const float2*)(bias + col);
            float o0 = a4[0] + bv.x, o1 = a4[1] + bv.y;
            float o2 = a4[2] + bv.x, o3 = a4[3] + bv.y;
            if (RESID) {
                float2 u = *(const float2*)(Rm + (size_t)row0*N + col);
                float2 v = *(const float2*)(Rm + (size_t)(row0+8)*N + col);
                o0 += u.x; o1 += u.y; o2 += v.x; o3 += v.y;
            }
            if (RELU) {
                o0 = fmaxf(o0, 0.f); o1 = fmaxf(o1, 0.f);
                o2 = fmaxf(o2, 0.f); o3 = fmaxf(o3, 0.f);
            }
            if (HOUT) {
                *(uint32_t*)(Ch + (size_t)row0*N + col)     = pack_h2(o0, o1);
                *(uint32_t*)(Ch + (size_t)(row0+8)*N + col) = pack_h2(o2, o3);
            } else {
                *(float2*)(Cf + (size_t)row0*N + col)     = make_float2(o0, o1);
                *(float2*)(Cf + (size_t)(row0+8)*N + col) = make_float2(o2, o3);
            }
        }
    }
}

// ---------------- Flash attention v2 (fp16 mma, causal) ----------------
// 64 q-rows x 64 kv-cols tiles; 4 warps (128 thr), warp owns 16 q-rows.
#define KP 72                           // pitch (halves) = 144 B
#define ATT_SMEM ((2*64*KP + 2*64*KP + 4*16*KP + 4*16*KP) * 2)

__global__ __launch_bounds__(128, 2)
void attn_kernel(const __half* __restrict__ qkv, __half* __restrict__ out)
{
    extern __shared__ __half sa[];
    __half* Ksm = sa;                    // [2][64][KP]
    __half* Vsm = Ksm + 2*64*KP;         // [2][64][KP]
    __half* Psm = Vsm + 2*64*KP;         // [4][16][KP]
    __half* Qsm = Psm + 4*16*KP;         // [4][16][KP]

    const int tid = threadIdx.x;
    const int w = tid >> 5, lane = tid & 31;
    const int g = lane >> 2, q = lane & 3;
    const int Lt = lane >> 3, Lr = lane & 7;
    const int qi = (gridDim.x - 1) - blockIdx.x;   // longest first
    const int h = blockIdx.y, b = blockIdx.z;
    const int qBase = qi * 64;
    const size_t bT = (size_t)b * TT;

    __half* Pw = Psm + w*16*KP;
    __half* Qw = Qsm + w*16*KP;

    // load Q tile (16 rows x 64 halves)
    {
        const __half* qg = qkv + (bT + qBase + w*16) * 3072 + h*64;
        #pragma unroll
        for (int i = 0; i < 4; i++) {
            int f = lane + i*32;
            int r = f >> 3, c8 = (f & 7) << 3;
            *(uint4*)&Qw[r*KP + c8] = *(const uint4*)(qg + (size_t)r*3072 + c8);
        }
    }
    __syncwarp();

    float m0 = NEG_INF, m1 = NEG_INF, l0 = 0.f, l1 = 0.f;
    float accO[8][4];
    #pragma unroll
    for (int i = 0; i < 8; i++)
        #pragma unroll
        for (int j = 0; j < 4; j++) accO[i][j] = 0.f;

    const int nT = qi + 1;
    const uint32_t skb = s2u(Ksm), svb = s2u(Vsm);
    const uint32_t lmq = s2u(Qw) + (uint32_t)(((((Lt & 1)*8) + Lr)*KP + (Lt >> 1)*8) * 2);
    const uint32_t lmp = s2u(Pw) + (uint32_t)(((((Lt & 1)*8) + Lr)*KP + (Lt >> 1)*8) * 2);
    const uint32_t lmk = skb + (uint32_t)((Lr*KP + (Lt & 1)*8) * 2);   // K frag base
    const uint32_t lmv = svb + (uint32_t)((((Lt & 1)*8 + Lr)*KP) * 2); // V frag base (trans)

    // prologue: kv tile 0 -> stage 0
    {
        const __half* kg = qkv + bT * 3072 + EMB + h*64;
        #pragma unroll
        for (int i = 0; i < 4; i++) {
            int f = tid + i*128;
            int r = f >> 3, c8 = (f & 7) << 3;
            cpa16(skb + (uint32_t)((r*KP + c8)*2), kg + (size_t)r*3072 + c8);
            cpa16(svb + (uint32_t)((r*KP + c8)*2), kg + (size_t)r*3072 + EMB + c8);
        }
        CP_COMMIT();
    }

    #pragma unroll 1
    for (int j = 0; j < nT; ++j) {
        if (j + 1 < nT) {
            const int st = (j + 1) & 1;
            const __half* kg = qkv + (bT + (size_t)(j+1)*64) * 3072 + EMB + h*64;
            #pragma unroll
            for (int i = 0; i < 4; i++) {
                int f = tid + i*128;
                int r = f >> 3, c8 = (f & 7) << 3;
                cpa16(skb + (uint32_t)(((st*64 + r)*KP + c8)*2), kg + (size_t)r*3072 + c8);
                cpa16(svb + (uint32_t)(((st*64 + r)*KP + c8)*2), kg + (size_t)r*3072 + EMB + c8);
            }
            CP_COMMIT();
            CP_WAIT(1);
        } else {
            CP_WAIT(0);
        }
        __syncthreads();

        const uint32_t kst = (uint32_t)((j & 1) * 64 * KP * 2);

        // ---- S = Q @ K^T : 8 n-tiles, 4 k16 steps ----
        float sacc[8][4];
        #pragma unroll
        for (int i = 0; i < 8; i++)
            #pragma unroll
            for (int jj = 0; jj < 4; jj++) sacc[i][jj] = 0.f;

        #pragma unroll
        for (int ks = 0; ks < 4; ks++) {
            const uint32_t kb = (uint32_t)(ks * 32);   // 16 halves
            uint32_t aq[4];
            ldm_x4(aq, lmq + kb);
            uint32_t bf[8][2];
            #pragma unroll
            for (int nt = 0; nt < 8; nt++)
                ldm_x2(bf[nt], lmk + kst + (uint32_t)(nt*8*KP*2) + kb);
            #pragma unroll
            for (int nt = 0; nt < 8; nt++)
                mma_f16(sacc[nt], aq, bf[nt]);
        }

        // scale + causal mask (diag tile only)
        const int r0 = qBase + w*16 + g;
        const int jb = j * 64;
        const bool diag = (j == qi);
        #pragma unroll
        for (int nt = 0; nt < 8; nt++) {
            sacc[nt][0] *= 0.125f; sacc[nt][1] *= 0.125f;
            sacc[nt][2] *= 0.125f; sacc[nt][3] *= 0.125f;
            if (diag) {
                const int c0 = jb + nt*8 + 2*q;
                if (c0     > r0    ) sacc[nt][0] = NEG_INF;
                if (c0 + 1 > r0    ) sacc[nt][1] = NEG_INF;
                if (c0     > r0 + 8) sacc[nt][2] = NEG_INF;
                if (c0 + 1 > r0 + 8) sacc[nt][3] = NEG_INF;
            }
        }

        // ---- online softmax in registers ----
        float ml0 = NEG_INF, ml1 = NEG_INF;
        #pragma unroll
        for (int nt = 0; nt < 8; nt++) {
            ml0 = fmaxf(ml0, fmaxf(sacc[nt][0], sacc[nt][1]));
            ml1 = fmaxf(ml1, fmaxf(sacc[nt][2], sacc[nt][3]));
        }
        ml0 = fmaxf(ml0, __shfl_xor_sync(0xffffffffu, ml0, 1));
        ml0 = fmaxf(ml0, __shfl_xor_sync(0xffffffffu, ml0, 2));
        ml1 = fmaxf(ml1, __shfl_xor_sync(0xffffffffu, ml1, 1));
        ml1 = fmaxf(ml1, __shfl_xor_sync(0xffffffffu, ml1, 2));
        const float mn0 = fmaxf(m0, ml0);
        const float mn1 = fmaxf(m1, ml1);
        const float a0 = __expf(m0 - mn0);
        const float a1 = __expf(m1 - mn1);
        float s0 = 0.f, s1 = 0.f;
        #pragma unroll
        for (int nt = 0; nt < 8; nt++) {
            sacc[nt][0] = __expf(sacc[nt][0] - mn0);
            sacc[nt][1] = __expf(sacc[nt][1] - mn0);
            sacc[nt][2] = __expf(sacc[nt][2] - mn1);
            sacc[nt][3] = __expf(sacc[nt][3] - mn1);
            s0 += sacc[nt][0] + sacc[nt][1];
            s1 += sacc[nt][2] + sacc[nt][3];
        }
        s0 += __shfl_xor_sync(0xffffffffu, s0, 1);
        s0 += __shfl_xor_sync(0xffffffffu, s0, 2);
        s1 += __shfl_xor_sync(0xffffffffu, s1, 1);
        s1 += __shfl_xor_sync(0xffffffffu, s1, 2);
        m0 = mn0; m1 = mn1;
        l0 = l0 * a0 + s0;
        l1 = l1 * a1 + s1;
        #pragma unroll
        for (int dt = 0; dt < 8; dt++) {
            accO[dt][0] *= a0; accO[dt][1] *= a0;
            accO[dt][2] *= a1; accO[dt][3] *= a1;
        }

        // ---- P (half) -> warp-private smem ----
        #pragma unroll
        for (int nt = 0; nt < 8; nt++) {
            const int c = nt*8 + 2*q;
            *(uint32_t*)&Pw[(g    )*KP + c] = pack_h2(sacc[nt][0], sacc[nt][1]);
            *(uint32_t*)&Pw[(g + 8)*KP + c] = pack_h2(sacc[nt][2], sacc[nt][3]);
        }
        __syncwarp();

        // ---- O += P @ V : A = P (ldm x4), B = V (ldm x2 trans) ----
        #pragma unroll
        for (int ks = 0; ks < 4; ks++) {
            const uint32_t kb = (uint32_t)(ks * 32);
            uint32_t af[4];
            ldm_x4(af, lmp + kb);
            const uint32_t vrow = lmv + kst + (uint32_t)(ks*16*KP*2);
            uint32_t bf[8][2];
            #pragma unroll
            for (int dt = 0; dt < 8; dt++)
                ldm_x2_t(bf[dt], vrow + (uint32_t)(dt*8*2));
            #pragma unroll
            for (int dt = 0; dt < 8; dt++)
                mma_f16(accO[dt], af, bf[dt]);
        }
        __syncwarp();
        __syncthreads();
    }

    // ---- finalize: divide by l, write half out [b,t,e] ----
    const float inv0 = 1.f / l0;
    const float inv1 = 1.f / l1;
    const size_t row0 = bT + qBase + w*16 + g;
    #pragma unroll
    for (int dt = 0; dt < 8; dt++) {
        const int c = h*64 + dt*8 + 2*q;
        *(uint32_t*)(out + row0*EMB + c)       = pack_h2(accO[dt][0]*inv0, accO[dt][1]*inv0);
        *(uint32_t*)(out + (row0 + 8)*EMB + c) = pack_h2(accO[dt][2]*inv1, accO[dt][3]*inv1);
    }
}

// ---------------- LayerNorm over last dim (1024) ----------------
__global__ __launch_bounds__(256)
void ln_kernel(const float* __restrict__ in, const float* __restrict__ g,
               const float* __restrict__ bb, float* __restrict__ out,
               __half* __restrict__ outh)
{
    const int row = blockIdx.x, tid = threadIdx.x;
    const float* rp = in + (size_t)row * EMB;
    float4 v = *(const float4*)(rp + tid*4);
    float s  = v.x + v.y + v.z + v.w;
    float sq = v.x*v.x + v.y*v.y + v.z*v.z + v.w*v.w;
    #pragma unroll
    for (int o = 16; o > 0; o >>= 1) {
        s  += __shfl_xor_sync(0xffffffffu, s,  o);
        sq += __shfl_xor_sync(0xffffffffu, sq, o);
    }
    __shared__ float ws[8], wq[8], stat[2];
    const int w = tid >> 5;
    if ((tid & 31) == 0) { ws[w] = s; wq[w] = sq; }
    __syncthreads();
    if (tid == 0) {
        float ts = 0.f, tq = 0.f;
        #pragma unroll
        for (int i = 0; i < 8; i++) { ts += ws[i]; tq += wq[i]; }
        float mean = ts * (1.f/EMB);
        float var  = tq * (1.f/EMB) - mean*mean;
        stat[0] = mean;
        stat[1] = rsqrtf(var + 1e-5f);
    }
    __syncthreads();
    const float mean = stat[0], rs = stat[1];
    float4 gv = *(const float4*)(g  + tid*4);
    float4 bv = *(const float4*)(bb + tid*4);
    float4 o;
    o.x = (v.x - mean)*rs*gv.x + bv.x;
    o.y = (v.y - mean)*rs*gv.y + bv.y;
    o.z = (v.z - mean)*rs*gv.z + bv.z;
    o.w = (v.w - mean)*rs*gv.w + bv.w;
    *(float4*)(out + (size_t)row*EMB + tid*4) = o;
    if (outh) {
        *(uint2*)(outh + (size_t)row*EMB + tid*4) =
            make_uint2(pack_h2(o.x, o.y), pack_h2(o.z, o.w));
    }
}

// ---------------- launch ----------------
extern "C" void kernel_launch(void* const* d_in, const int* in_sizes, int n_in,
                              void* d_out, int out_size)
{
    const float* x   = (const float*)d_in[0];
    const float* wat = (const float*)d_in[1];
    const float* bat = (const float*)d_in[2];
    const float* wpr = (const float*)d_in[3];
    const float* bpr = (const float*)d_in[4];
    const float* l1g = (const float*)d_in[5];
    const float* l1b = (const float*)d_in[6];
    const float* wf1 = (const float*)d_in[7];
    const float* bf1 = (const float*)d_in[8];
    const float* wf2 = (const float*)d_in[9];
    const float* bf2 = (const float*)d_in[10];
    const float* l2g = (const float*)d_in[11];
    const float* l2b = (const float*)d_in[12];

    static __half *xh = nullptr, *qkvh, *atth, *x1h, *ffh, *watT, *wprT, *wf1T, *wf2T;
    static float *res1, *x1f, *res2;
    if (!xh) {
        cudaGetSymbolAddress((void**)&xh,   g_xh);
        cudaGetSymbolAddress((void**)&qkvh, g_qkvh);
        cudaGetSymbolAddress((void**)&atth, g_atth);
        cudaGetSymbolAddress((void**)&res1, g_res1);
        cudaGetSymbolAddress((void**)&x1f,  g_x1f);
        cudaGetSymbolAddress((void**)&x1h,  g_x1h);
        cudaGetSymbolAddress((void**)&ffh,  g_ffh);
        cudaGetSymbolAddress((void**)&res2, g_res2);
        cudaGetSymbolAddress((void**)&watT, g_watT);
        cudaGetSymbolAddress((void**)&wprT, g_wprT);
        cudaGetSymbolAddress((void**)&wf1T, g_wf1T);
        cudaGetSymbolAddress((void**)&wf2T, g_wf2T);
        cudaFuncSetAttribute(attn_kernel, cudaFuncAttributeMaxDynamicSharedMemorySize, ATT_SMEM);
        cudaFuncSetAttribute(gemm_mma<false,false,true>, cudaFuncAttributeMaxDynamicSharedMemorySize, GSMEM);
        cudaFuncSetAttribute(gemm_mma<false,true,false>, cudaFuncAttributeMaxDynamicSharedMemorySize, GSMEM);
        cudaFuncSetAttribute(gemm_mma<true,false,true>,  cudaFuncAttributeMaxDynamicSharedMemorySize, GSMEM);
    }

    // x -> half; weights transpose -> half
    cvt_half<<<MR*EMB/1024, 256>>>((const float4*)x, (uint2*)xh);
    transpose_cvt<<<dim3(3*EMB/32, EMB/32), dim3(32,8)>>>(wat, watT, EMB, 3*EMB);
    transpose_cvt<<<dim3(EMB/32,   EMB/32), dim3(32,8)>>>(wpr, wprT, EMB, EMB);
    transpose_cvt<<<dim3(DFF/32,   EMB/32), dim3(32,8)>>>(wf1, wf1T, EMB, DFF);
    transpose_cvt<<<dim3(EMB/32,   DFF/32), dim3(32,8)>>>(wf2, wf2T, DFF, EMB);

    // 1. QKV projection -> half
    gemm_mma<false,false,true><<<dim3(3*EMB/128, MR/128), 256, GSMEM>>>(xh, watT, bat, nullptr, nullptr, qkvh, 3*EMB, EMB);
    // 2. causal flash attention -> half
    attn_kernel<<<dim3(TT/64, NH, BB), 128, ATT_SMEM>>>(qkvh, atth);
    // 3. output proj + residual(x) -> fp32
    gemm_mma<false,true,false><<<dim3(EMB/128, MR/128), 256, GSMEM>>>(atth, wprT, bpr, x, res1, nullptr, EMB, EMB);
    // 4. LN1 -> x1f (fp32) + x1h (half)
    ln_kernel<<<MR, 256>>>(res1, l1g, l1b, x1f, x1h);
    // 5. FF1 + ReLU -> half
    gemm_mma<true,false,true><<<dim3(DFF/128, MR/128), 256, GSMEM>>>(x1h, wf1T, bf1, nullptr, nullptr, ffh, DFF, EMB);
    // 6. FF2 + residual(x1f) -> fp32
    gemm_mma<false,true,false><<<dim3(EMB/128, MR/128), 256, GSMEM>>>(ffh, wf2T, bf2, x1f, res2, nullptr, EMB, DFF);
    // 7. LN2 -> out
    ln_kernel<<<MR, 256>>>(res2, l2g, l2b, (float*)d_out, nullptr);
}